// round 12
// baseline (speedup 1.0000x reference)
#include <cuda_runtime.h>
#include <cuda_bf16.h>
#include <cstdint>

// RecursiveEncoder — mma.sync bf16 3-term split + nc-sorted child skipping.
// R11: PT=32/NT=256 -> 2 CTAs/SM (102KB smem each); LPT (descending-nc)
//      block order; same per-warp GEMM code as R9.

#define NT    256
#define PT    32
#define GRID  1024
#define MAXC  10
#define B_N   32768

#define ASTR  264          // A row stride (bf16): conflict-free LDSM
#define WBUF  12288        // one W chunk buffer: 256 rows * 48B

// ---- smem offsets (bytes) ----
#define OFF_AHI   0          // 32*264*2 = 16896
#define OFF_ALO   16896
#define OFF_WH    33792      // 2 bufs * 12288
#define OFF_WL    58368      // 2 bufs * 12288
#define OFF_BOX   82944      // 32*10*4 = 1280
#define OFF_WBOX  84224      // 10*256*4 = 10240
#define OFF_BBOX  94464
#define OFF_B1    95488
#define OFF_B2    96512
#define OFF_BS1   97536
#define OFF_BMU   98560
#define OFF_BVAR  99584
#define OFF_SEM   100608     // 32*10*4 = 1280
#define OFF_NC    101888     // 128
#define OFF_PERM  102016     // 128
#define OFF_MAXNC 102144     // 16
#define SMEM_SZ   102160

__device__ __nv_bfloat16 g_WT_hi[5 * 65536];   // [layer][n][k]
__device__ __nv_bfloat16 g_WT_lo[5 * 65536];
__device__ int g_cnt[16];
__device__ int g_rank[B_N];
__device__ int g_perm[B_N];

static __device__ __forceinline__ uint32_t smem_u32(const void* p) {
    uint32_t a;
    asm("{ .reg .u64 t; cvta.to.shared.u64 t, %1; cvt.u32.u64 %0, t; }"
        : "=r"(a) : "l"(p));
    return a;
}
static __device__ __forceinline__ void mma16816(float d[4], const uint32_t a[4],
                                                uint32_t b0, uint32_t b1)
{
    asm volatile(
        "mma.sync.aligned.m16n8k16.row.col.f32.bf16.bf16.f32 "
        "{%0,%1,%2,%3}, {%4,%5,%6,%7}, {%8,%9}, {%0,%1,%2,%3};"
        : "+f"(d[0]), "+f"(d[1]), "+f"(d[2]), "+f"(d[3])
        : "r"(a[0]), "r"(a[1]), "r"(a[2]), "r"(a[3]), "r"(b0), "r"(b1));
}
static __device__ __forceinline__ void ldsm_x4(uint32_t r[4], uint32_t addr) {
    asm volatile("ldmatrix.sync.aligned.m8n8.x4.shared.b16 {%0,%1,%2,%3}, [%4];"
                 : "=r"(r[0]), "=r"(r[1]), "=r"(r[2]), "=r"(r[3]) : "r"(addr));
}

// ---- prep kernels ----
__global__ void prep_weights(const float* __restrict__ W1, const float* __restrict__ W2,
                             const float* __restrict__ Ws1, const float* __restrict__ Wmu,
                             const float* __restrict__ Wvar)
{
    int idx = blockIdx.x * blockDim.x + threadIdx.x;
    int l = idx >> 16;
    int e = idx & 65535;
    int n = e >> 8, k = e & 255;
    const float* src = (l == 0) ? W1 : (l == 1) ? W2 : (l == 2) ? Ws1 : (l == 3) ? Wmu : Wvar;
    float v = src[k * 256 + n];
    __nv_bfloat16 h = __float2bfloat16(v);
    g_WT_hi[idx] = h;
    g_WT_lo[idx] = __float2bfloat16(v - __bfloat162float(h));
}
__global__ void sort_zero() { if (threadIdx.x < 16) g_cnt[threadIdx.x] = 0; }
__global__ void sort_count(const int* __restrict__ nc) {
    int i = blockIdx.x * blockDim.x + threadIdx.x;
    if (i < B_N) g_rank[i] = atomicAdd(&g_cnt[nc[i] - 1], 1);
}
// LPT: descending-nc order -> heavy (nc=10) blocks launch first
__global__ void sort_scatter(const int* __restrict__ nc) {
    int i = blockIdx.x * blockDim.x + threadIdx.x;
    if (i < B_N) {
        int b = nc[i] - 1;
        int base = 0;
        #pragma unroll
        for (int j = 0; j < MAXC; j++) base += (j > b) ? g_cnt[j] : 0;
        g_perm[base + g_rank[i]] = i;
    }
}

// ---- full K=256 GEMM: C[16 rows x 64 cols per warp], 3-term bf16 split ----
static __device__ __forceinline__ void gemm_tc(char* sm, uint32_t smb,
                                               const __nv_bfloat16* __restrict__ whi,
                                               const __nv_bfloat16* __restrict__ wlo,
                                               int t, int lane, int wm, int wn,
                                               float C[8][4])
{
    #pragma unroll
    for (int nt = 0; nt < 8; nt++)
        #pragma unroll
        for (int q = 0; q < 4; q++) C[nt][q] = 0.0f;

    const int arow = (lane & 7) + ((lane >> 3) & 1) * 8;
    const int akoff = (lane >> 4) * 8;
    uint32_t aHi = smb + OFF_AHI + (uint32_t)(((wm * 16 + arow) * ASTR + akoff) * 2);
    uint32_t aLo = aHi + (OFF_ALO - OFF_AHI);
    const int brow = (lane & 7) + ((lane >> 4) & 1) * 8;
    const int bkoff = ((lane >> 3) & 1) * 8;
    const uint32_t bRel = (uint32_t)(((wn * 64 + brow) * 24 + bkoff) * 2);
    const uint32_t wh0 = smb + OFF_WH, wl0 = smb + OFF_WL;

    // W chunk: thread t owns weight row n = t (256 threads, 256 rows)
    const uint4* gh = (const uint4*)(whi + t * 256);
    const uint4* gl = (const uint4*)(wlo + t * 256);
    const uint32_t stoff = (uint32_t)(t * 48);

    uint4 ph0 = gh[0], ph1 = gh[1], pl0 = gl[0], pl1 = gl[1];
    *(uint4*)(sm + OFF_WH + stoff)      = ph0;
    *(uint4*)(sm + OFF_WH + stoff + 16) = ph1;
    *(uint4*)(sm + OFF_WL + stoff)      = pl0;
    *(uint4*)(sm + OFF_WL + stoff + 16) = pl1;
    __syncthreads();

    #pragma unroll 1
    for (int c = 0; c < 16; c++) {
        if (c < 15) {
            ph0 = gh[(c + 1) * 2]; ph1 = gh[(c + 1) * 2 + 1];
            pl0 = gl[(c + 1) * 2]; pl1 = gl[(c + 1) * 2 + 1];
        }

        const uint32_t bsel = (uint32_t)(c & 1) * WBUF;
        uint32_t ah[4], al[4];
        ldsm_x4(ah, aHi + c * 32);
        ldsm_x4(al, aLo + c * 32);
        uint32_t bh[4][4], bl[4][4];
        #pragma unroll
        for (int nt2 = 0; nt2 < 4; nt2++) {
            ldsm_x4(bh[nt2], wh0 + bsel + bRel + nt2 * 768);
            ldsm_x4(bl[nt2], wl0 + bsel + bRel + nt2 * 768);
        }
        #pragma unroll
        for (int nt2 = 0; nt2 < 4; nt2++) {
            mma16816(C[nt2 * 2],     ah, bh[nt2][0], bh[nt2][1]);
            mma16816(C[nt2 * 2 + 1], ah, bh[nt2][2], bh[nt2][3]);
        }
        #pragma unroll
        for (int nt2 = 0; nt2 < 4; nt2++) {
            mma16816(C[nt2 * 2],     al, bh[nt2][0], bh[nt2][1]);
            mma16816(C[nt2 * 2 + 1], al, bh[nt2][2], bh[nt2][3]);
        }
        #pragma unroll
        for (int nt2 = 0; nt2 < 4; nt2++) {
            mma16816(C[nt2 * 2],     ah, bl[nt2][0], bl[nt2][1]);
            mma16816(C[nt2 * 2 + 1], ah, bl[nt2][2], bl[nt2][3]);
        }

        if (c < 15) {
            const uint32_t nsel = (uint32_t)((c + 1) & 1) * WBUF;
            *(uint4*)(sm + OFF_WH + nsel + stoff)      = ph0;
            *(uint4*)(sm + OFF_WH + nsel + stoff + 16) = ph1;
            *(uint4*)(sm + OFF_WL + nsel + stoff)      = pl0;
            *(uint4*)(sm + OFF_WL + nsel + stoff + 16) = pl1;
        }
        __syncthreads();
    }
}

static __device__ __forceinline__ void split_pair(__nv_bfloat16* Ahi, __nv_bfloat16* Alo,
                                                  int idx, float s0, float s1)
{
    __nv_bfloat162 h2 = __float22bfloat162_rn(make_float2(s0, s1));
    float r0 = s0 - __bfloat162float(__low2bfloat16(h2));
    float r1 = s1 - __bfloat162float(__high2bfloat16(h2));
    __nv_bfloat162 l2 = __float22bfloat162_rn(make_float2(r0, r1));
    *(uint32_t*)&Ahi[idx] = *(uint32_t*)&h2;
    *(uint32_t*)&Alo[idx] = *(uint32_t*)&l2;
}

__global__ void __launch_bounds__(NT, 2)
recenc_tc_kernel(const float* __restrict__ box_input,
                 const float* __restrict__ eps,
                 const float* __restrict__ W_box,
                 const float* __restrict__ b_box,
                 const float* __restrict__ W1,
                 const float* __restrict__ b1,
                 const float* __restrict__ b2,
                 const float* __restrict__ bs1,
                 const float* __restrict__ bmu,
                 const float* __restrict__ bvar,
                 const int*   __restrict__ sem_ids,
                 const int*   __restrict__ n_children,
                 float*       __restrict__ out)
{
    extern __shared__ char sm[];
    const uint32_t smb = smem_u32(sm);
    __nv_bfloat16* Ahi = (__nv_bfloat16*)(sm + OFF_AHI);
    __nv_bfloat16* Alo = (__nv_bfloat16*)(sm + OFF_ALO);
    float* boxS  = (float*)(sm + OFF_BOX);
    float* wboxS = (float*)(sm + OFF_WBOX);
    float* bboxS = (float*)(sm + OFF_BBOX);
    float* b1S   = (float*)(sm + OFF_B1);
    float* b2S   = (float*)(sm + OFF_B2);
    float* bs1S  = (float*)(sm + OFF_BS1);
    float* bmuS  = (float*)(sm + OFF_BMU);
    float* bvarS = (float*)(sm + OFF_BVAR);
    int*   semS  = (int*)(sm + OFF_SEM);
    int*   ncS   = (int*)(sm + OFF_NC);
    int*   permS = (int*)(sm + OFF_PERM);
    int*   maxncS = (int*)(sm + OFF_MAXNC);

    const int t = threadIdx.x;
    const int lane = t & 31;
    const int wid = t >> 5;
    const int wm = wid >> 2;      // 0..1 -> rows wm*16 + [0,16)
    const int wn = wid & 3;       // 0..3 -> cols wn*64 + [0,64)
    const int b0 = blockIdx.x * PT;

    // ---- stage constants + permuted per-parent data ----
    for (int i = t; i < 10 * 256; i += NT) wboxS[i] = W_box[i];
    if (t < 256) {
        bboxS[t] = b_box[t];
        b1S[t]   = b1[t];
        b2S[t]   = b2[t];
        bs1S[t]  = bs1[t];
        bmuS[t]  = bmu[t];
        bvarS[t] = bvar[t];
    }
    if (t < PT) {
        int pid = g_perm[b0 + t];
        permS[t] = pid;
        ncS[t] = n_children[pid];
    }
    __syncthreads();
    for (int i = t; i < PT * 10; i += NT) semS[i] = sem_ids[permS[i / 10] * 10 + (i % 10)];
    if (t == 0) {
        int mx = 0;
        for (int i = 0; i < PT; i++) mx = max(mx, ncS[i]);
        maxncS[0] = mx;
    }
    __syncthreads();
    const int maxnc = maxncS[0];

    const int fp = t & 127;
    const int f0 = fp * 2;
    const int r_half0 = wm * 16 + (lane >> 2);
    const int colq = wn * 64 + (lane & 3) * 2;

    float C[8][4];
    float macc[8][4];
    #pragma unroll
    for (int nt = 0; nt < 8; nt++)
        #pragma unroll
        for (int q = 0; q < 4; q++) macc[nt][q] = 0.0f;

    // ---- children loop (bounded by block max nc) ----
    for (int m = 0; m < maxnc; m++) {
        for (int i = t; i < PT * 10; i += NT)
            boxS[i] = box_input[permS[i / 10] * 100 + m * 10 + (i % 10)];
        __syncthreads();

        // leaf = relu(box @ Wbox + bbox): 16 pairs per thread, fixed column pair
        float2 bbp = *(const float2*)&bboxS[f0];
        #pragma unroll 4
        for (int u = 0; u < 16; u++) {
            int r = (t >> 7) + u * 2;
            float s0 = bbp.x, s1 = bbp.y;
            const float* bx = &boxS[r * 10];
            #pragma unroll
            for (int q = 0; q < 10; q++) {
                float b = bx[q];
                float2 w = *(const float2*)&wboxS[q * 256 + f0];
                s0 += b * w.x;
                s1 += b * w.y;
            }
            split_pair(Ahi, Alo, r * ASTR + f0, fmaxf(s0, 0.0f), fmaxf(s1, 0.0f));
        }

        gemm_tc(sm, smb, g_WT_hi, g_WT_lo, t, lane, wm, wn, C);

        // epilogue in registers: macc = max(macc, relu(C + W1[256+sem] + b1))
        #pragma unroll
        for (int half = 0; half < 2; half++) {
            int r = r_half0 + half * 8;
            if (m < ncS[r]) {
                const float* wrow = W1 + ((256 + semS[r * 10 + m]) << 8);
                #pragma unroll
                for (int nt = 0; nt < 8; nt++) {
                    int col = colq + nt * 8;
                    float2 w  = *(const float2*)&wrow[col];
                    float2 bb = *(const float2*)&b1S[col];
                    macc[nt][half * 2 + 0] = fmaxf(macc[nt][half * 2 + 0],
                        fmaxf(C[nt][half * 2 + 0] + w.x + bb.x, 0.0f));
                    macc[nt][half * 2 + 1] = fmaxf(macc[nt][half * 2 + 1],
                        fmaxf(C[nt][half * 2 + 1] + w.y + bb.y, 0.0f));
                }
            }
        }
    }

    #define FRAGS_TO_A(SRC, BIAS, RELU)                                        \
        do {                                                                   \
            _Pragma("unroll")                                                  \
            for (int half = 0; half < 2; half++) {                             \
                int r = r_half0 + half * 8;                                    \
                _Pragma("unroll")                                              \
                for (int nt = 0; nt < 8; nt++) {                               \
                    int col = colq + nt * 8;                                   \
                    float2 bb = *(const float2*)&(BIAS)[col];                  \
                    float v0 = (SRC)[nt][half * 2 + 0] + bb.x;                 \
                    float v1 = (SRC)[nt][half * 2 + 1] + bb.y;                 \
                    if (RELU) { v0 = fmaxf(v0, 0.0f); v1 = fmaxf(v1, 0.0f); }  \
                    split_pair(Ahi, Alo, r * ASTR + col, v0, v1);              \
                }                                                              \
            }                                                                  \
        } while (0)

    // ---- parent_feat = relu(X @ W2 + b2) ----
    #pragma unroll
    for (int half = 0; half < 2; half++) {
        int r = r_half0 + half * 8;
        #pragma unroll
        for (int nt = 0; nt < 8; nt++) {
            int col = colq + nt * 8;
            split_pair(Ahi, Alo, r * ASTR + col,
                       macc[nt][half * 2 + 0], macc[nt][half * 2 + 1]);
        }
    }
    gemm_tc(sm, smb, g_WT_hi + 1 * 65536, g_WT_lo + 1 * 65536, t, lane, wm, wn, C);
    FRAGS_TO_A(C, b2S, 1);

    // ---- enc = relu(P @ Ws1 + bs1) ----
    gemm_tc(sm, smb, g_WT_hi + 2 * 65536, g_WT_lo + 2 * 65536, t, lane, wm, wn, C);
    FRAGS_TO_A(C, bs1S, 1);

    // ---- mu = enc @ Wmu + bmu (kept in regs; A holds enc) ----
    gemm_tc(sm, smb, g_WT_hi + 3 * 65536, g_WT_lo + 3 * 65536, t, lane, wm, wn, C);
    float mu[8][4];
    #pragma unroll
    for (int half = 0; half < 2; half++)
        #pragma unroll
        for (int nt = 0; nt < 8; nt++) {
            int col = colq + nt * 8;
            float2 bb = *(const float2*)&bmuS[col];
            mu[nt][half * 2 + 0] = C[nt][half * 2 + 0] + bb.x;
            mu[nt][half * 2 + 1] = C[nt][half * 2 + 1] + bb.y;
        }

    // ---- logvar = enc @ Wvar + bvar; sampler epilogue direct to GMEM ----
    gemm_tc(sm, smb, g_WT_hi + 4 * 65536, g_WT_lo + 4 * 65536, t, lane, wm, wn, C);
    #pragma unroll
    for (int half = 0; half < 2; half++) {
        int r = r_half0 + half * 8;
        int pid = permS[r];
        #pragma unroll
        for (int nt = 0; nt < 8; nt++) {
            int col = colq + nt * 8;
            float2 bb = *(const float2*)&bvarS[col];
            float2 e  = *(const float2*)&eps[pid * 256 + col];
            float lvx = C[nt][half * 2 + 0] + bb.x;
            float lvy = C[nt][half * 2 + 1] + bb.y;
            float mvx = mu[nt][half * 2 + 0];
            float mvy = mu[nt][half * 2 + 1];
            float sdx = expf(0.5f * lvx);
            float sdy = expf(0.5f * lvy);
            float2 samp, kld;
            samp.x = e.x * sdx + mvx;
            samp.y = e.y * sdy + mvy;
            kld.x = 1.0f + lvx - mvx * mvx - sdx * sdx;
            kld.y = 1.0f + lvy - mvy * mvy - sdy * sdy;
            *(float2*)&out[pid * 512 + col]       = samp;
            *(float2*)&out[pid * 512 + 256 + col] = kld;
        }
    }
}

// ================= launch =================
extern "C" void kernel_launch(void* const* d_in, const int* in_sizes, int n_in,
                              void* d_out, int out_size)
{
    const float* box   = (const float*)d_in[0];
    const float* eps   = (const float*)d_in[1];
    const float* W_box = (const float*)d_in[2];
    const float* b_box = (const float*)d_in[3];
    const float* W1    = (const float*)d_in[4];
    const float* b1    = (const float*)d_in[5];
    const float* W2    = (const float*)d_in[6];
    const float* b2    = (const float*)d_in[7];
    const float* Ws1   = (const float*)d_in[8];
    const float* bs1   = (const float*)d_in[9];
    const float* Wmu   = (const float*)d_in[10];
    const float* bmu   = (const float*)d_in[11];
    const float* Wvar  = (const float*)d_in[12];
    const float* bvar  = (const float*)d_in[13];
    const int*   sem   = (const int*)d_in[14];
    const int*   nc    = (const int*)d_in[15];
    float* out = (float*)d_out;

    prep_weights<<<(5 * 65536) / 256, 256>>>(W1, W2, Ws1, Wmu, Wvar);
    sort_zero<<<1, 32>>>();
    sort_count<<<B_N / 256, 256>>>(nc);
    sort_scatter<<<B_N / 256, 256>>>(nc);

    cudaFuncSetAttribute(recenc_tc_kernel,
                         cudaFuncAttributeMaxDynamicSharedMemorySize, SMEM_SZ);
    recenc_tc_kernel<<<GRID, NT, SMEM_SZ>>>(
        box, eps, W_box, b_box, W1, b1, b2, bs1, bmu, bvar, sem, nc, out);
}

// round 13
// speedup vs baseline: 2.5408x; 2.5408x over previous
#include <cuda_runtime.h>
#include <cuda_bf16.h>
#include <cstdint>

// RecursiveEncoder — mma.sync bf16 3-term split + nc-sorted child skipping.
// R13: weights pre-packed in GLOBAL memory in per-thread fragment order;
//      B frags loaded by coalesced LDG.64 directly to registers.
//      -> no W smem, no STS, barrier-free chunk loop. PT=64/NT=512 (R9 shape),
//      LPT (descending-nc) block order.

#define NT    512
#define PT    64
#define GRID  512
#define MAXC  10
#define B_N   32768

#define ASTR  264          // A row stride (bf16): conflict-free LDSM

// ---- smem offsets (bytes) ----
#define OFF_AHI   0          // 64*264*2 = 33792
#define OFF_ALO   33792
#define OFF_BOX   67584      // 64*10*4 = 2560
#define OFF_WBOX  70144      // 10*256*4 = 10240
#define OFF_BBOX  80384
#define OFF_B1    81408
#define OFF_B2    82432
#define OFF_BS1   83456
#define OFF_BMU   84480
#define OFF_BVAR  85504
#define OFF_SEM   86528      // 2560
#define OFF_NC    89088      // 256
#define OFF_PERM  89344      // 256
#define OFF_MAXNC 89600      // 16
#define SMEM_SZ   89616

// Packed B fragments: [layer][chunk c:16][ngroup:32][lane:32] = uint2
//  uint2.x = bf16x2 (k0,k0+1), .y = (k0+8,k0+9) at n = ng*8 + lane>>2,
//  k0 = c*16 + (lane&3)*2   — exactly the mma.m16n8k16 B fragment.
__device__ uint2 g_pk_hi[5 * 16384];
__device__ uint2 g_pk_lo[5 * 16384];
__device__ int g_cnt[16];
__device__ int g_rank[B_N];
__device__ int g_perm[B_N];

static __device__ __forceinline__ uint32_t smem_u32(const void* p) {
    uint32_t a;
    asm("{ .reg .u64 t; cvta.to.shared.u64 t, %1; cvt.u32.u64 %0, t; }"
        : "=r"(a) : "l"(p));
    return a;
}
static __device__ __forceinline__ void mma16816(float d[4], const uint32_t a[4],
                                                uint32_t b0, uint32_t b1)
{
    asm volatile(
        "mma.sync.aligned.m16n8k16.row.col.f32.bf16.bf16.f32 "
        "{%0,%1,%2,%3}, {%4,%5,%6,%7}, {%8,%9}, {%0,%1,%2,%3};"
        : "+f"(d[0]), "+f"(d[1]), "+f"(d[2]), "+f"(d[3])
        : "r"(a[0]), "r"(a[1]), "r"(a[2]), "r"(a[3]), "r"(b0), "r"(b1));
}
static __device__ __forceinline__ void ldsm_x4(uint32_t r[4], uint32_t addr) {
    asm volatile("ldmatrix.sync.aligned.m8n8.x4.shared.b16 {%0,%1,%2,%3}, [%4];"
                 : "=r"(r[0]), "=r"(r[1]), "=r"(r[2]), "=r"(r[3]) : "r"(addr));
}

// ---- prep: pack transposed hi/lo split weights in fragment order ----
__global__ void prep_pack(const float* __restrict__ W1, const float* __restrict__ W2,
                          const float* __restrict__ Ws1, const float* __restrict__ Wmu,
                          const float* __restrict__ Wvar)
{
    int idx = blockIdx.x * blockDim.x + threadIdx.x;   // 81920
    int lane = idx & 31;
    int ng   = (idx >> 5) & 31;
    int c    = (idx >> 10) & 15;
    int l    = idx >> 14;
    const float* src = (l == 0) ? W1 : (l == 1) ? W2 : (l == 2) ? Ws1 : (l == 3) ? Wmu : Wvar;
    int n  = ng * 8 + (lane >> 2);
    int kb = c * 16 + (lane & 3) * 2;
    float v0 = src[(kb + 0) * 256 + n];
    float v1 = src[(kb + 1) * 256 + n];
    float v2 = src[(kb + 8) * 256 + n];
    float v3 = src[(kb + 9) * 256 + n];
    __nv_bfloat162 h01 = __float22bfloat162_rn(make_float2(v0, v1));
    __nv_bfloat162 h23 = __float22bfloat162_rn(make_float2(v2, v3));
    float r0 = v0 - __bfloat162float(__low2bfloat16(h01));
    float r1 = v1 - __bfloat162float(__high2bfloat16(h01));
    float r2 = v2 - __bfloat162float(__low2bfloat16(h23));
    float r3 = v3 - __bfloat162float(__high2bfloat16(h23));
    __nv_bfloat162 l01 = __float22bfloat162_rn(make_float2(r0, r1));
    __nv_bfloat162 l23 = __float22bfloat162_rn(make_float2(r2, r3));
    g_pk_hi[idx] = make_uint2(*(uint32_t*)&h01, *(uint32_t*)&h23);
    g_pk_lo[idx] = make_uint2(*(uint32_t*)&l01, *(uint32_t*)&l23);
}
__global__ void sort_zero() { if (threadIdx.x < 16) g_cnt[threadIdx.x] = 0; }
__global__ void sort_count(const int* __restrict__ nc) {
    int i = blockIdx.x * blockDim.x + threadIdx.x;
    if (i < B_N) g_rank[i] = atomicAdd(&g_cnt[nc[i] - 1], 1);
}
// LPT: descending-nc order -> heavy blocks first
__global__ void sort_scatter(const int* __restrict__ nc) {
    int i = blockIdx.x * blockDim.x + threadIdx.x;
    if (i < B_N) {
        int b = nc[i] - 1;
        int base = 0;
        #pragma unroll
        for (int j = 0; j < MAXC; j++) base += (j > b) ? g_cnt[j] : 0;
        g_perm[base + g_rank[i]] = i;
    }
}

// ---- full K=256 GEMM: C[16 rows x 64 cols per warp], barrier-free inside.
//      A from smem via LDSM; B from packed global via coalesced LDG.64. ----
static __device__ __forceinline__ void gemm_tc(uint32_t smb, int layer,
                                               int lane, int wm, int wn,
                                               float C[8][4])
{
    #pragma unroll
    for (int nt = 0; nt < 8; nt++)
        #pragma unroll
        for (int q = 0; q < 4; q++) C[nt][q] = 0.0f;

    const int arow = (lane & 7) + ((lane >> 3) & 1) * 8;
    const int akoff = (lane >> 4) * 8;
    uint32_t aHi = smb + OFF_AHI + (uint32_t)(((wm * 16 + arow) * ASTR + akoff) * 2);
    uint32_t aLo = aHi + (OFF_ALO - OFF_AHI);

    const uint2* __restrict__ bh = g_pk_hi + layer * 16384 + (wn * 8) * 32 + lane;
    const uint2* __restrict__ bl = g_pk_lo + layer * 16384 + (wn * 8) * 32 + lane;

    #pragma unroll 1
    for (int c = 0; c < 16; c++) {
        uint2 BH[8], BL[8];
        #pragma unroll
        for (int nt = 0; nt < 8; nt++) BH[nt] = bh[c * 1024 + nt * 32];
        #pragma unroll
        for (int nt = 0; nt < 8; nt++) BL[nt] = bl[c * 1024 + nt * 32];
        uint32_t ah[4], al[4];
        ldsm_x4(ah, aHi + c * 32);
        ldsm_x4(al, aLo + c * 32);
        #pragma unroll
        for (int nt = 0; nt < 8; nt++) mma16816(C[nt], ah, BH[nt].x, BH[nt].y);
        #pragma unroll
        for (int nt = 0; nt < 8; nt++) mma16816(C[nt], al, BH[nt].x, BH[nt].y);
        #pragma unroll
        for (int nt = 0; nt < 8; nt++) mma16816(C[nt], ah, BL[nt].x, BL[nt].y);
    }
}

static __device__ __forceinline__ void split_pair(__nv_bfloat16* Ahi, __nv_bfloat16* Alo,
                                                  int idx, float s0, float s1)
{
    __nv_bfloat162 h2 = __float22bfloat162_rn(make_float2(s0, s1));
    float r0 = s0 - __bfloat162float(__low2bfloat16(h2));
    float r1 = s1 - __bfloat162float(__high2bfloat16(h2));
    __nv_bfloat162 l2 = __float22bfloat162_rn(make_float2(r0, r1));
    *(uint32_t*)&Ahi[idx] = *(uint32_t*)&h2;
    *(uint32_t*)&Alo[idx] = *(uint32_t*)&l2;
}

__global__ void __launch_bounds__(NT, 1)
recenc_tc_kernel(const float* __restrict__ box_input,
                 const float* __restrict__ eps,
                 const float* __restrict__ W_box,
                 const float* __restrict__ b_box,
                 const float* __restrict__ W1,
                 const float* __restrict__ b1,
                 const float* __restrict__ b2,
                 const float* __restrict__ bs1,
                 const float* __restrict__ bmu,
                 const float* __restrict__ bvar,
                 const int*   __restrict__ sem_ids,
                 const int*   __restrict__ n_children,
                 float*       __restrict__ out)
{
    extern __shared__ char sm[];
    const uint32_t smb = smem_u32(sm);
    __nv_bfloat16* Ahi = (__nv_bfloat16*)(sm + OFF_AHI);
    __nv_bfloat16* Alo = (__nv_bfloat16*)(sm + OFF_ALO);
    float* boxS  = (float*)(sm + OFF_BOX);
    float* wboxS = (float*)(sm + OFF_WBOX);
    float* bboxS = (float*)(sm + OFF_BBOX);
    float* b1S   = (float*)(sm + OFF_B1);
    float* b2S   = (float*)(sm + OFF_B2);
    float* bs1S  = (float*)(sm + OFF_BS1);
    float* bmuS  = (float*)(sm + OFF_BMU);
    float* bvarS = (float*)(sm + OFF_BVAR);
    int*   semS  = (int*)(sm + OFF_SEM);
    int*   ncS   = (int*)(sm + OFF_NC);
    int*   permS = (int*)(sm + OFF_PERM);
    int*   maxncS = (int*)(sm + OFF_MAXNC);

    const int t = threadIdx.x;
    const int lane = t & 31;
    const int wid = t >> 5;
    const int wm = wid >> 2;      // 0..3 -> rows wm*16 + [0,16)
    const int wn = wid & 3;       // 0..3 -> cols wn*64 + [0,64)
    const int b0 = blockIdx.x * PT;

    // ---- stage constants + permuted per-parent data ----
    for (int i = t; i < 10 * 256; i += NT) wboxS[i] = W_box[i];
    if (t < 256) {
        bboxS[t] = b_box[t];
        b1S[t]   = b1[t];
        b2S[t]   = b2[t];
        bs1S[t]  = bs1[t];
        bmuS[t]  = bmu[t];
        bvarS[t] = bvar[t];
    }
    if (t < PT) {
        int pid = g_perm[b0 + t];
        permS[t] = pid;
        ncS[t] = n_children[pid];
    }
    __syncthreads();
    for (int i = t; i < PT * 10; i += NT) semS[i] = sem_ids[permS[i / 10] * 10 + (i % 10)];
    if (t == 0) {
        int mx = 0;
        for (int i = 0; i < PT; i++) mx = max(mx, ncS[i]);
        maxncS[0] = mx;
    }
    __syncthreads();
    const int maxnc = maxncS[0];

    const int fp = t & 127;
    const int f0 = fp * 2;
    const int r_half0 = wm * 16 + (lane >> 2);
    const int colq = wn * 64 + (lane & 3) * 2;

    float C[8][4];
    float macc[8][4];
    #pragma unroll
    for (int nt = 0; nt < 8; nt++)
        #pragma unroll
        for (int q = 0; q < 4; q++) macc[nt][q] = 0.0f;

    // ---- children loop (bounded by block max nc) ----
    for (int m = 0; m < maxnc; m++) {
        // stage boxS (prior iteration's post-gemm barrier protects consumers)
        for (int i = t; i < PT * 10; i += NT)
            boxS[i] = box_input[permS[i / 10] * 100 + m * 10 + (i % 10)];
        __syncthreads();   // boxS visible

        // leaf = relu(box @ Wbox + bbox): 16 pairs per thread, fixed column pair
        float2 bbp = *(const float2*)&bboxS[f0];
        #pragma unroll 4
        for (int u = 0; u < 16; u++) {
            int r = (t >> 7) + u * 4;
            float s0 = bbp.x, s1 = bbp.y;
            const float* bx = &boxS[r * 10];
            #pragma unroll
            for (int q = 0; q < 10; q++) {
                float b = bx[q];
                float2 w = *(const float2*)&wboxS[q * 256 + f0];
                s0 += b * w.x;
                s1 += b * w.y;
            }
            split_pair(Ahi, Alo, r * ASTR + f0, fmaxf(s0, 0.0f), fmaxf(s1, 0.0f));
        }
        __syncthreads();   // A visible to all warps

        gemm_tc(smb, 0, lane, wm, wn, C);
        __syncthreads();   // all warps done reading A/boxS

        // epilogue in registers: macc = max(macc, relu(C + W1[256+sem] + b1))
        #pragma unroll
        for (int half = 0; half < 2; half++) {
            int r = r_half0 + half * 8;
            if (m < ncS[r]) {
                const float* wrow = W1 + ((256 + semS[r * 10 + m]) << 8);
                #pragma unroll
                for (int nt = 0; nt < 8; nt++) {
                    int col = colq + nt * 8;
                    float2 w  = *(const float2*)&wrow[col];
                    float2 bb = *(const float2*)&b1S[col];
                    macc[nt][half * 2 + 0] = fmaxf(macc[nt][half * 2 + 0],
                        fmaxf(C[nt][half * 2 + 0] + w.x + bb.x, 0.0f));
                    macc[nt][half * 2 + 1] = fmaxf(macc[nt][half * 2 + 1],
                        fmaxf(C[nt][half * 2 + 1] + w.y + bb.y, 0.0f));
                }
            }
        }
    }

    #define FRAGS_TO_A(SRC, BIAS, RELU)                                        \
        do {                                                                   \
            _Pragma("unroll")                                                  \
            for (int half = 0; half < 2; half++) {                             \
                int r = r_half0 + half * 8;                                    \
                _Pragma("unroll")                                              \
                for (int nt = 0; nt < 8; nt++) {                               \
                    int col = colq + nt * 8;                                   \
                    float2 bb = *(const float2*)&(BIAS)[col];                  \
                    float v0 = (SRC)[nt][half * 2 + 0] + bb.x;                 \
                    float v1 = (SRC)[nt][half * 2 + 1] + bb.y;                 \
                    if (RELU) { v0 = fmaxf(v0, 0.0f); v1 = fmaxf(v1, 0.0f); }  \
                    split_pair(Ahi, Alo, r * ASTR + col, v0, v1);              \
                }                                                              \
            }                                                                  \
        } while (0)

    // ---- parent_feat = relu(X @ W2 + b2) ----
    #pragma unroll
    for (int half = 0; half < 2; half++) {
        int r = r_half0 + half * 8;
        #pragma unroll
        for (int nt = 0; nt < 8; nt++) {
            int col = colq + nt * 8;
            split_pair(Ahi, Alo, r * ASTR + col,
                       macc[nt][half * 2 + 0], macc[nt][half * 2 + 1]);
        }
    }
    __syncthreads();
    gemm_tc(smb, 1, lane, wm, wn, C);
    __syncthreads();
    FRAGS_TO_A(C, b2S, 1);
    __syncthreads();

    // ---- enc = relu(P @ Ws1 + bs1) ----
    gemm_tc(smb, 2, lane, wm, wn, C);
    __syncthreads();
    FRAGS_TO_A(C, bs1S, 1);
    __syncthreads();

    // ---- mu = enc @ Wmu + bmu (kept in regs; A holds enc) ----
    gemm_tc(smb, 3, lane, wm, wn, C);
    float mu[8][4];
    #pragma unroll
    for (int half = 0; half < 2; half++)
        #pragma unroll
        for (int nt = 0; nt < 8; nt++) {
            int col = colq + nt * 8;
            float2 bb = *(const float2*)&bmuS[col];
            mu[nt][half * 2 + 0] = C[nt][half * 2 + 0] + bb.x;
            mu[nt][half * 2 + 1] = C[nt][half * 2 + 1] + bb.y;
        }

    // ---- logvar = enc @ Wvar + bvar (A untouched since enc write) ----
    gemm_tc(smb, 4, lane, wm, wn, C);
    #pragma unroll
    for (int half = 0; half < 2; half++) {
        int r = r_half0 + half * 8;
        int pid = permS[r];
        #pragma unroll
        for (int nt = 0; nt < 8; nt++) {
            int col = colq + nt * 8;
            float2 bb = *(const float2*)&bvarS[col];
            float2 e  = *(const float2*)&eps[pid * 256 + col];
            float lvx = C[nt][half * 2 + 0] + bb.x;
            float lvy = C[nt][half * 2 + 1] + bb.y;
            float mvx = mu[nt][half * 2 + 0];
            float mvy = mu[nt][half * 2 + 1];
            float sdx = expf(0.5f * lvx);
            float sdy = expf(0.5f * lvy);
            float2 samp, kld;
            samp.x = e.x * sdx + mvx;
            samp.y = e.y * sdy + mvy;
            kld.x = 1.0f + lvx - mvx * mvx - sdx * sdx;
            kld.y = 1.0f + lvy - mvy * mvy - sdy * sdy;
            *(float2*)&out[pid * 512 + col]       = samp;
            *(float2*)&out[pid * 512 + 256 + col] = kld;
        }
    }
}

// ================= launch =================
extern "C" void kernel_launch(void* const* d_in, const int* in_sizes, int n_in,
                              void* d_out, int out_size)
{
    const float* box   = (const float*)d_in[0];
    const float* eps   = (const float*)d_in[1];
    const float* W_box = (const float*)d_in[2];
    const float* b_box = (const float*)d_in[3];
    const float* W1    = (const float*)d_in[4];
    const float* b1    = (const float*)d_in[5];
    const float* W2    = (const float*)d_in[6];
    const float* b2    = (const float*)d_in[7];
    const float* Ws1   = (const float*)d_in[8];
    const float* bs1   = (const float*)d_in[9];
    const float* Wmu   = (const float*)d_in[10];
    const float* bmu   = (const float*)d_in[11];
    const float* Wvar  = (const float*)d_in[12];
    const float* bvar  = (const float*)d_in[13];
    const int*   sem   = (const int*)d_in[14];
    const int*   nc    = (const int*)d_in[15];
    float* out = (float*)d_out;

    prep_pack<<<320, 256>>>(W1, W2, Ws1, Wmu, Wvar);
    sort_zero<<<1, 32>>>();
    sort_count<<<B_N / 256, 256>>>(nc);
    sort_scatter<<<B_N / 256, 256>>>(nc);

    cudaFuncSetAttribute(recenc_tc_kernel,
                         cudaFuncAttributeMaxDynamicSharedMemorySize, SMEM_SZ);
    recenc_tc_kernel<<<GRID, NT, SMEM_SZ>>>(
        box, eps, W_box, b_box, W1, b1, b2, bs1, bmu, bvar, sem, nc, out);
}

// round 14
// speedup vs baseline: 2.6742x; 1.0525x over previous
#include <cuda_runtime.h>
#include <cuda_bf16.h>
#include <cstdint>

// RecursiveEncoder — mma.sync bf16 3-term split + nc-sorted child skipping.
// R14: PT=32/NT=256 with 2 CTAs/SM (cross-CTA overlap of serial phases);
//      all child boxes staged once; packed-global B fragments (R13 core).

#define NT    256
#define PT    32
#define GRID  1024
#define MAXC  10
#define B_N   32768

#define ASTR  264          // A row stride (bf16): conflict-free LDSM

// ---- smem offsets (bytes) ----
#define OFF_AHI   0          // 32*264*2 = 16896
#define OFF_ALO   16896
#define OFF_BOX   33792      // 32*100*4 = 12800 (ALL children)
#define OFF_WBOX  46592      // 10*256*4 = 10240
#define OFF_BBOX  56832
#define OFF_B1    57856
#define OFF_B2    58880
#define OFF_BS1   59904
#define OFF_BMU   60928
#define OFF_BVAR  61952
#define OFF_SEM   62976      // 32*10*4 = 1280
#define OFF_NC    64256      // 128
#define OFF_PERM  64384      // 128
#define OFF_MAXNC 64512      // 16
#define SMEM_SZ   64528

// Packed B fragments: [layer][chunk c:16][ngroup:32][lane:32] = uint2
__device__ uint2 g_pk_hi[5 * 16384];
__device__ uint2 g_pk_lo[5 * 16384];
__device__ int g_cnt[16];
__device__ int g_rank[B_N];
__device__ int g_perm[B_N];

static __device__ __forceinline__ uint32_t smem_u32(const void* p) {
    uint32_t a;
    asm("{ .reg .u64 t; cvta.to.shared.u64 t, %1; cvt.u32.u64 %0, t; }"
        : "=r"(a) : "l"(p));
    return a;
}
static __device__ __forceinline__ void mma16816(float d[4], const uint32_t a[4],
                                                uint32_t b0, uint32_t b1)
{
    asm volatile(
        "mma.sync.aligned.m16n8k16.row.col.f32.bf16.bf16.f32 "
        "{%0,%1,%2,%3}, {%4,%5,%6,%7}, {%8,%9}, {%0,%1,%2,%3};"
        : "+f"(d[0]), "+f"(d[1]), "+f"(d[2]), "+f"(d[3])
        : "r"(a[0]), "r"(a[1]), "r"(a[2]), "r"(a[3]), "r"(b0), "r"(b1));
}
static __device__ __forceinline__ void ldsm_x4(uint32_t r[4], uint32_t addr) {
    asm volatile("ldmatrix.sync.aligned.m8n8.x4.shared.b16 {%0,%1,%2,%3}, [%4];"
                 : "=r"(r[0]), "=r"(r[1]), "=r"(r[2]), "=r"(r[3]) : "r"(addr));
}

// ---- prep: pack transposed hi/lo split weights in fragment order ----
__global__ void prep_pack(const float* __restrict__ W1, const float* __restrict__ W2,
                          const float* __restrict__ Ws1, const float* __restrict__ Wmu,
                          const float* __restrict__ Wvar)
{
    int idx = blockIdx.x * blockDim.x + threadIdx.x;   // 81920
    int lane = idx & 31;
    int ng   = (idx >> 5) & 31;
    int c    = (idx >> 10) & 15;
    int l    = idx >> 14;
    const float* src = (l == 0) ? W1 : (l == 1) ? W2 : (l == 2) ? Ws1 : (l == 3) ? Wmu : Wvar;
    int n  = ng * 8 + (lane >> 2);
    int kb = c * 16 + (lane & 3) * 2;
    float v0 = src[(kb + 0) * 256 + n];
    float v1 = src[(kb + 1) * 256 + n];
    float v2 = src[(kb + 8) * 256 + n];
    float v3 = src[(kb + 9) * 256 + n];
    __nv_bfloat162 h01 = __float22bfloat162_rn(make_float2(v0, v1));
    __nv_bfloat162 h23 = __float22bfloat162_rn(make_float2(v2, v3));
    float r0 = v0 - __bfloat162float(__low2bfloat16(h01));
    float r1 = v1 - __bfloat162float(__high2bfloat16(h01));
    float r2 = v2 - __bfloat162float(__low2bfloat16(h23));
    float r3 = v3 - __bfloat162float(__high2bfloat16(h23));
    __nv_bfloat162 l01 = __float22bfloat162_rn(make_float2(r0, r1));
    __nv_bfloat162 l23 = __float22bfloat162_rn(make_float2(r2, r3));
    g_pk_hi[idx] = make_uint2(*(uint32_t*)&h01, *(uint32_t*)&h23);
    g_pk_lo[idx] = make_uint2(*(uint32_t*)&l01, *(uint32_t*)&l23);
}
__global__ void sort_zero() { if (threadIdx.x < 16) g_cnt[threadIdx.x] = 0; }
__global__ void sort_count(const int* __restrict__ nc) {
    int i = blockIdx.x * blockDim.x + threadIdx.x;
    if (i < B_N) g_rank[i] = atomicAdd(&g_cnt[nc[i] - 1], 1);
}
// LPT: descending-nc order -> heavy blocks first
__global__ void sort_scatter(const int* __restrict__ nc) {
    int i = blockIdx.x * blockDim.x + threadIdx.x;
    if (i < B_N) {
        int b = nc[i] - 1;
        int base = 0;
        #pragma unroll
        for (int j = 0; j < MAXC; j++) base += (j > b) ? g_cnt[j] : 0;
        g_perm[base + g_rank[i]] = i;
    }
}

// ---- full K=256 GEMM: C[16 rows x 64 cols per warp], barrier-free inside ----
static __device__ __forceinline__ void gemm_tc(uint32_t smb, int layer,
                                               int lane, int wm, int wn,
                                               float C[8][4])
{
    #pragma unroll
    for (int nt = 0; nt < 8; nt++)
        #pragma unroll
        for (int q = 0; q < 4; q++) C[nt][q] = 0.0f;

    const int arow = (lane & 7) + ((lane >> 3) & 1) * 8;
    const int akoff = (lane >> 4) * 8;
    uint32_t aHi = smb + OFF_AHI + (uint32_t)(((wm * 16 + arow) * ASTR + akoff) * 2);
    uint32_t aLo = aHi + (OFF_ALO - OFF_AHI);

    const uint2* __restrict__ bh = g_pk_hi + layer * 16384 + (wn * 8) * 32 + lane;
    const uint2* __restrict__ bl = g_pk_lo + layer * 16384 + (wn * 8) * 32 + lane;

    #pragma unroll 1
    for (int c = 0; c < 16; c++) {
        uint2 BH[8], BL[8];
        #pragma unroll
        for (int nt = 0; nt < 8; nt++) BH[nt] = bh[c * 1024 + nt * 32];
        #pragma unroll
        for (int nt = 0; nt < 8; nt++) BL[nt] = bl[c * 1024 + nt * 32];
        uint32_t ah[4], al[4];
        ldsm_x4(ah, aHi + c * 32);
        ldsm_x4(al, aLo + c * 32);
        #pragma unroll
        for (int nt = 0; nt < 8; nt++) mma16816(C[nt], ah, BH[nt].x, BH[nt].y);
        #pragma unroll
        for (int nt = 0; nt < 8; nt++) mma16816(C[nt], al, BH[nt].x, BH[nt].y);
        #pragma unroll
        for (int nt = 0; nt < 8; nt++) mma16816(C[nt], ah, BL[nt].x, BL[nt].y);
    }
}

static __device__ __forceinline__ void split_pair(__nv_bfloat16* Ahi, __nv_bfloat16* Alo,
                                                  int idx, float s0, float s1)
{
    __nv_bfloat162 h2 = __float22bfloat162_rn(make_float2(s0, s1));
    float r0 = s0 - __bfloat162float(__low2bfloat16(h2));
    float r1 = s1 - __bfloat162float(__high2bfloat16(h2));
    __nv_bfloat162 l2 = __float22bfloat162_rn(make_float2(r0, r1));
    *(uint32_t*)&Ahi[idx] = *(uint32_t*)&h2;
    *(uint32_t*)&Alo[idx] = *(uint32_t*)&l2;
}

__global__ void __launch_bounds__(NT, 2)
recenc_tc_kernel(const float* __restrict__ box_input,
                 const float* __restrict__ eps,
                 const float* __restrict__ W_box,
                 const float* __restrict__ b_box,
                 const float* __restrict__ W1,
                 const float* __restrict__ b1,
                 const float* __restrict__ b2,
                 const float* __restrict__ bs1,
                 const float* __restrict__ bmu,
                 const float* __restrict__ bvar,
                 const int*   __restrict__ sem_ids,
                 const int*   __restrict__ n_children,
                 float*       __restrict__ out)
{
    extern __shared__ char sm[];
    const uint32_t smb = smem_u32(sm);
    __nv_bfloat16* Ahi = (__nv_bfloat16*)(sm + OFF_AHI);
    __nv_bfloat16* Alo = (__nv_bfloat16*)(sm + OFF_ALO);
    float* boxS  = (float*)(sm + OFF_BOX);
    float* wboxS = (float*)(sm + OFF_WBOX);
    float* bboxS = (float*)(sm + OFF_BBOX);
    float* b1S   = (float*)(sm + OFF_B1);
    float* b2S   = (float*)(sm + OFF_B2);
    float* bs1S  = (float*)(sm + OFF_BS1);
    float* bmuS  = (float*)(sm + OFF_BMU);
    float* bvarS = (float*)(sm + OFF_BVAR);
    int*   semS  = (int*)(sm + OFF_SEM);
    int*   ncS   = (int*)(sm + OFF_NC);
    int*   permS = (int*)(sm + OFF_PERM);
    int*   maxncS = (int*)(sm + OFF_MAXNC);

    const int t = threadIdx.x;
    const int lane = t & 31;
    const int wid = t >> 5;
    const int wm = wid >> 2;      // 0..1 -> rows wm*16 + [0,16)
    const int wn = wid & 3;       // 0..3 -> cols wn*64 + [0,64)
    const int b0 = blockIdx.x * PT;

    // ---- stage constants + permuted per-parent data ----
    for (int i = t; i < 10 * 256; i += NT) wboxS[i] = W_box[i];
    bboxS[t] = b_box[t];
    b1S[t]   = b1[t];
    b2S[t]   = b2[t];
    bs1S[t]  = bs1[t];
    bmuS[t]  = bmu[t];
    bvarS[t] = bvar[t];
    if (t < PT) {
        int pid = g_perm[b0 + t];
        permS[t] = pid;
        ncS[t] = n_children[pid];
    }
    __syncthreads();
    for (int i = t; i < PT * 10; i += NT) semS[i] = sem_ids[permS[i / 10] * 10 + (i % 10)];
    // stage ALL children's boxes once: [r][100]
    for (int i = t; i < PT * 100; i += NT) boxS[i] = box_input[permS[i / 100] * 100 + (i % 100)];
    if (t == 0) {
        int mx = 0;
        for (int i = 0; i < PT; i++) mx = max(mx, ncS[i]);
        maxncS[0] = mx;
    }
    __syncthreads();
    const int maxnc = maxncS[0];

    const int fp = t & 127;
    const int f0 = fp * 2;
    const int r_half0 = wm * 16 + (lane >> 2);
    const int colq = wn * 64 + (lane & 3) * 2;

    float C[8][4];
    float macc[8][4];
    #pragma unroll
    for (int nt = 0; nt < 8; nt++)
        #pragma unroll
        for (int q = 0; q < 4; q++) macc[nt][q] = 0.0f;

    // ---- children loop (bounded by block max nc), 2 barriers per child ----
    #pragma unroll 1
    for (int m = 0; m < maxnc; m++) {
        // leaf = relu(box @ Wbox + bbox): 16 pairs per thread, fixed column pair
        float2 bbp = *(const float2*)&bboxS[f0];
        #pragma unroll 4
        for (int u = 0; u < 16; u++) {
            int r = (t >> 7) + u * 2;
            float s0 = bbp.x, s1 = bbp.y;
            const float* bx = &boxS[r * 100 + m * 10];
            #pragma unroll
            for (int q = 0; q < 10; q++) {
                float b = bx[q];
                float2 w = *(const float2*)&wboxS[q * 256 + f0];
                s0 += b * w.x;
                s1 += b * w.y;
            }
            split_pair(Ahi, Alo, r * ASTR + f0, fmaxf(s0, 0.0f), fmaxf(s1, 0.0f));
        }
        __syncthreads();   // A visible to all warps

        gemm_tc(smb, 0, lane, wm, wn, C);
        __syncthreads();   // all warps done reading A

        // epilogue in registers: macc = max(macc, relu(C + W1[256+sem] + b1))
        #pragma unroll
        for (int half = 0; half < 2; half++) {
            int r = r_half0 + half * 8;
            if (m < ncS[r]) {
                const float* wrow = W1 + ((256 + semS[r * 10 + m]) << 8);
                #pragma unroll
                for (int nt = 0; nt < 8; nt++) {
                    int col = colq + nt * 8;
                    float2 w  = *(const float2*)&wrow[col];
                    float2 bb = *(const float2*)&b1S[col];
                    macc[nt][half * 2 + 0] = fmaxf(macc[nt][half * 2 + 0],
                        fmaxf(C[nt][half * 2 + 0] + w.x + bb.x, 0.0f));
                    macc[nt][half * 2 + 1] = fmaxf(macc[nt][half * 2 + 1],
                        fmaxf(C[nt][half * 2 + 1] + w.y + bb.y, 0.0f));
                }
            }
        }
    }

    #define FRAGS_TO_A(SRC, BIAS, RELU)                                        \
        do {                                                                   \
            _Pragma("unroll")                                                  \
            for (int half = 0; half < 2; half++) {                             \
                int r = r_half0 + half * 8;                                    \
                _Pragma("unroll")                                              \
                for (int nt = 0; nt < 8; nt++) {                               \
                    int col = colq + nt * 8;                                   \
                    float2 bb = *(const float2*)&(BIAS)[col];                  \
                    float v0 = (SRC)[nt][half * 2 + 0] + bb.x;                 \
                    float v1 = (SRC)[nt][half * 2 + 1] + bb.y;                 \
                    if (RELU) { v0 = fmaxf(v0, 0.0f); v1 = fmaxf(v1, 0.0f); }  \
                    split_pair(Ahi, Alo, r * ASTR + col, v0, v1);              \
                }                                                              \
            }                                                                  \
        } while (0)

    // ---- parent_feat = relu(X @ W2 + b2) ----
    #pragma unroll
    for (int half = 0; half < 2; half++) {
        int r = r_half0 + half * 8;
        #pragma unroll
        for (int nt = 0; nt < 8; nt++) {
            int col = colq + nt * 8;
            split_pair(Ahi, Alo, r * ASTR + col,
                       macc[nt][half * 2 + 0], macc[nt][half * 2 + 1]);
        }
    }
    __syncthreads();
    gemm_tc(smb, 1, lane, wm, wn, C);
    __syncthreads();
    FRAGS_TO_A(C, b2S, 1);
    __syncthreads();

    // ---- enc = relu(P @ Ws1 + bs1) ----
    gemm_tc(smb, 2, lane, wm, wn, C);
    __syncthreads();
    FRAGS_TO_A(C, bs1S, 1);
    __syncthreads();

    // ---- mu = enc @ Wmu + bmu (kept in regs; A holds enc) ----
    gemm_tc(smb, 3, lane, wm, wn, C);
    float mu[8][4];
    #pragma unroll
    for (int half = 0; half < 2; half++)
        #pragma unroll
        for (int nt = 0; nt < 8; nt++) {
            int col = colq + nt * 8;
            float2 bb = *(const float2*)&bmuS[col];
            mu[nt][half * 2 + 0] = C[nt][half * 2 + 0] + bb.x;
            mu[nt][half * 2 + 1] = C[nt][half * 2 + 1] + bb.y;
        }

    // ---- logvar = enc @ Wvar + bvar (A untouched since enc write) ----
    gemm_tc(smb, 4, lane, wm, wn, C);
    #pragma unroll
    for (int half = 0; half < 2; half++) {
        int r = r_half0 + half * 8;
        int pid = permS[r];
        #pragma unroll
        for (int nt = 0; nt < 8; nt++) {
            int col = colq + nt * 8;
            float2 bb = *(const float2*)&bvarS[col];
            float2 e  = *(const float2*)&eps[pid * 256 + col];
            float lvx = C[nt][half * 2 + 0] + bb.x;
            float lvy = C[nt][half * 2 + 1] + bb.y;
            float mvx = mu[nt][half * 2 + 0];
            float mvy = mu[nt][half * 2 + 1];
            float sdx = expf(0.5f * lvx);
            float sdy = expf(0.5f * lvy);
            float2 samp, kld;
            samp.x = e.x * sdx + mvx;
            samp.y = e.y * sdy + mvy;
            kld.x = 1.0f + lvx - mvx * mvx - sdx * sdx;
            kld.y = 1.0f + lvy - mvy * mvy - sdy * sdy;
            *(float2*)&out[pid * 512 + col]       = samp;
            *(float2*)&out[pid * 512 + 256 + col] = kld;
        }
    }
}

// ================= launch =================
extern "C" void kernel_launch(void* const* d_in, const int* in_sizes, int n_in,
                              void* d_out, int out_size)
{
    const float* box   = (const float*)d_in[0];
    const float* eps   = (const float*)d_in[1];
    const float* W_box = (const float*)d_in[2];
    const float* b_box = (const float*)d_in[3];
    const float* W1    = (const float*)d_in[4];
    const float* b1    = (const float*)d_in[5];
    const float* W2    = (const float*)d_in[6];
    const float* b2    = (const float*)d_in[7];
    const float* Ws1   = (const float*)d_in[8];
    const float* bs1   = (const float*)d_in[9];
    const float* Wmu   = (const float*)d_in[10];
    const float* bmu   = (const float*)d_in[11];
    const float* Wvar  = (const float*)d_in[12];
    const float* bvar  = (const float*)d_in[13];
    const int*   sem   = (const int*)d_in[14];
    const int*   nc    = (const int*)d_in[15];
    float* out = (float*)d_out;

    prep_pack<<<320, 256>>>(W1, W2, Ws1, Wmu, Wvar);
    sort_zero<<<1, 32>>>();
    sort_count<<<B_N / 256, 256>>>(nc);
    sort_scatter<<<B_N / 256, 256>>>(nc);

    cudaFuncSetAttribute(recenc_tc_kernel,
                         cudaFuncAttributeMaxDynamicSharedMemorySize, SMEM_SZ);
    recenc_tc_kernel<<<GRID, NT, SMEM_SZ>>>(
        box, eps, W_box, b_box, W1, b1, b2, bs1, bmu, bvar, sem, nc, out);
}

// round 15
// speedup vs baseline: 2.9933x; 1.1193x over previous
#include <cuda_runtime.h>
#include <cuda_bf16.h>
#include <cstdint>

// RecursiveEncoder — mma.sync bf16 3-term split + nc-sorted child skipping.
// R15: leaf box-encoder on tensor cores (K=16 padded MMA); B fragments packed
//      as uint4 (hi+lo in one LDG.128). PT=32/NT=256, 2 CTAs/SM, LPT order.

#define NT    256
#define PT    32
#define GRID  1024
#define MAXC  10
#define B_N   32768

#define ASTR  264          // A row stride (bf16): conflict-free LDSM
#define BXSTR 24           // box tile row stride (bf16): 48B -> conflict-free LDSM

// ---- smem offsets (bytes) ----
#define OFF_AHI   0          // 32*264*2 = 16896
#define OFF_ALO   16896      // -> 33792
#define OFF_BXH   33792      // 10*32*24*2 = 15360 -> 49152
#define OFF_BXL   49152      // -> 64512
#define OFF_BBOX  64512      // 1024
#define OFF_B1    65536
#define OFF_B2    66560
#define OFF_BS1   67584
#define OFF_BMU   68608
#define OFF_BVAR  69632
#define OFF_SEM   70656      // 1280
#define OFF_NC    71936      // 128
#define OFF_PERM  72064      // 128
#define OFF_MAXNC 72192      // 16
#define SMEM_SZ   72208

// Packed B fragments: [layer][chunk c:16][ngroup:32][lane:32] uint4 =
//   (hi_k01, hi_k89, lo_k01, lo_k89) for n = ng*8 + lane>>2, k0 = c*16+(lane&3)*2
__device__ uint4 g_pk[5 * 16384];
__device__ uint4 g_pkbox[1024];          // W_box fragments, K padded 10->16
__device__ int g_cnt[16];
__device__ int g_rank[B_N];
__device__ int g_perm[B_N];

static __device__ __forceinline__ uint32_t smem_u32(const void* p) {
    uint32_t a;
    asm("{ .reg .u64 t; cvta.to.shared.u64 t, %1; cvt.u32.u64 %0, t; }"
        : "=r"(a) : "l"(p));
    return a;
}
static __device__ __forceinline__ void mma16816(float d[4], const uint32_t a[4],
                                                uint32_t b0, uint32_t b1)
{
    asm volatile(
        "mma.sync.aligned.m16n8k16.row.col.f32.bf16.bf16.f32 "
        "{%0,%1,%2,%3}, {%4,%5,%6,%7}, {%8,%9}, {%0,%1,%2,%3};"
        : "+f"(d[0]), "+f"(d[1]), "+f"(d[2]), "+f"(d[3])
        : "r"(a[0]), "r"(a[1]), "r"(a[2]), "r"(a[3]), "r"(b0), "r"(b1));
}
static __device__ __forceinline__ void ldsm_x4(uint32_t r[4], uint32_t addr) {
    asm volatile("ldmatrix.sync.aligned.m8n8.x4.shared.b16 {%0,%1,%2,%3}, [%4];"
                 : "=r"(r[0]), "=r"(r[1]), "=r"(r[2]), "=r"(r[3]) : "r"(addr));
}

// ---- prep: pack transposed hi/lo split weights in fragment order (uint4) ----
__global__ void prep_pack(const float* __restrict__ W1, const float* __restrict__ W2,
                          const float* __restrict__ Ws1, const float* __restrict__ Wmu,
                          const float* __restrict__ Wvar)
{
    int idx = blockIdx.x * blockDim.x + threadIdx.x;   // 81920
    int lane = idx & 31;
    int ng   = (idx >> 5) & 31;
    int c    = (idx >> 10) & 15;
    int l    = idx >> 14;
    const float* src = (l == 0) ? W1 : (l == 1) ? W2 : (l == 2) ? Ws1 : (l == 3) ? Wmu : Wvar;
    int n  = ng * 8 + (lane >> 2);
    int kb = c * 16 + (lane & 3) * 2;
    float v0 = src[(kb + 0) * 256 + n];
    float v1 = src[(kb + 1) * 256 + n];
    float v2 = src[(kb + 8) * 256 + n];
    float v3 = src[(kb + 9) * 256 + n];
    __nv_bfloat162 h01 = __float22bfloat162_rn(make_float2(v0, v1));
    __nv_bfloat162 h23 = __float22bfloat162_rn(make_float2(v2, v3));
    float r0 = v0 - __bfloat162float(__low2bfloat16(h01));
    float r1 = v1 - __bfloat162float(__high2bfloat16(h01));
    float r2 = v2 - __bfloat162float(__low2bfloat16(h23));
    float r3 = v3 - __bfloat162float(__high2bfloat16(h23));
    __nv_bfloat162 l01 = __float22bfloat162_rn(make_float2(r0, r1));
    __nv_bfloat162 l23 = __float22bfloat162_rn(make_float2(r2, r3));
    g_pk[idx] = make_uint4(*(uint32_t*)&h01, *(uint32_t*)&h23,
                           *(uint32_t*)&l01, *(uint32_t*)&l23);
}
// W_box fragments: n = ng*8+lane>>2 (256 feats), k0 = (lane&3)*2, K padded to 16
__global__ void prep_pack_box(const float* __restrict__ W_box)
{
    int idx = blockIdx.x * blockDim.x + threadIdx.x;   // 1024
    int lane = idx & 31;
    int ng   = idx >> 5;
    int n  = ng * 8 + (lane >> 2);
    int kb = (lane & 3) * 2;
    float v0 = (kb + 0 < 10) ? W_box[(kb + 0) * 256 + n] : 0.0f;
    float v1 = (kb + 1 < 10) ? W_box[(kb + 1) * 256 + n] : 0.0f;
    float v2 = (kb + 8 < 10) ? W_box[(kb + 8) * 256 + n] : 0.0f;
    float v3 = (kb + 9 < 10) ? W_box[(kb + 9) * 256 + n] : 0.0f;
    __nv_bfloat162 h01 = __float22bfloat162_rn(make_float2(v0, v1));
    __nv_bfloat162 h23 = __float22bfloat162_rn(make_float2(v2, v3));
    float r0 = v0 - __bfloat162float(__low2bfloat16(h01));
    float r1 = v1 - __bfloat162float(__high2bfloat16(h01));
    float r2 = v2 - __bfloat162float(__low2bfloat16(h23));
    float r3 = v3 - __bfloat162float(__high2bfloat16(h23));
    __nv_bfloat162 l01 = __float22bfloat162_rn(make_float2(r0, r1));
    __nv_bfloat162 l23 = __float22bfloat162_rn(make_float2(r2, r3));
    g_pkbox[idx] = make_uint4(*(uint32_t*)&h01, *(uint32_t*)&h23,
                              *(uint32_t*)&l01, *(uint32_t*)&l23);
}
__global__ void sort_zero() { if (threadIdx.x < 16) g_cnt[threadIdx.x] = 0; }
__global__ void sort_count(const int* __restrict__ nc) {
    int i = blockIdx.x * blockDim.x + threadIdx.x;
    if (i < B_N) g_rank[i] = atomicAdd(&g_cnt[nc[i] - 1], 1);
}
__global__ void sort_scatter(const int* __restrict__ nc) {
    int i = blockIdx.x * blockDim.x + threadIdx.x;
    if (i < B_N) {
        int b = nc[i] - 1;
        int base = 0;
        #pragma unroll
        for (int j = 0; j < MAXC; j++) base += (j > b) ? g_cnt[j] : 0;
        g_perm[base + g_rank[i]] = i;
    }
}

// ---- full K=256 GEMM: C[16 rows x 64 cols per warp], barrier-free inside ----
static __device__ __forceinline__ void gemm_tc(uint32_t smb, int layer,
                                               int lane, int wm, int wn,
                                               float C[8][4])
{
    #pragma unroll
    for (int nt = 0; nt < 8; nt++)
        #pragma unroll
        for (int q = 0; q < 4; q++) C[nt][q] = 0.0f;

    const int arow = (lane & 7) + ((lane >> 3) & 1) * 8;
    const int akoff = (lane >> 4) * 8;
    uint32_t aHi = smb + OFF_AHI + (uint32_t)(((wm * 16 + arow) * ASTR + akoff) * 2);
    uint32_t aLo = aHi + (OFF_ALO - OFF_AHI);

    const uint4* __restrict__ bp = g_pk + layer * 16384 + (wn * 8) * 32 + lane;

    #pragma unroll 1
    for (int c = 0; c < 16; c++) {
        uint4 B[8];
        #pragma unroll
        for (int nt = 0; nt < 8; nt++) B[nt] = bp[c * 1024 + nt * 32];
        uint32_t ah[4], al[4];
        ldsm_x4(ah, aHi + c * 32);
        ldsm_x4(al, aLo + c * 32);
        #pragma unroll
        for (int nt = 0; nt < 8; nt++) mma16816(C[nt], ah, B[nt].x, B[nt].y);
        #pragma unroll
        for (int nt = 0; nt < 8; nt++) mma16816(C[nt], al, B[nt].x, B[nt].y);
        #pragma unroll
        for (int nt = 0; nt < 8; nt++) mma16816(C[nt], ah, B[nt].z, B[nt].w);
    }
}

static __device__ __forceinline__ void split_pair(__nv_bfloat16* Ahi, __nv_bfloat16* Alo,
                                                  int idx, float s0, float s1)
{
    __nv_bfloat162 h2 = __float22bfloat162_rn(make_float2(s0, s1));
    float r0 = s0 - __bfloat162float(__low2bfloat16(h2));
    float r1 = s1 - __bfloat162float(__high2bfloat16(h2));
    __nv_bfloat162 l2 = __float22bfloat162_rn(make_float2(r0, r1));
    *(uint32_t*)&Ahi[idx] = *(uint32_t*)&h2;
    *(uint32_t*)&Alo[idx] = *(uint32_t*)&l2;
}

__global__ void __launch_bounds__(NT, 2)
recenc_tc_kernel(const float* __restrict__ box_input,
                 const float* __restrict__ eps,
                 const float* __restrict__ W_box,
                 const float* __restrict__ b_box,
                 const float* __restrict__ W1,
                 const float* __restrict__ b1,
                 const float* __restrict__ b2,
                 const float* __restrict__ bs1,
                 const float* __restrict__ bmu,
                 const float* __restrict__ bvar,
                 const int*   __restrict__ sem_ids,
                 const int*   __restrict__ n_children,
                 float*       __restrict__ out)
{
    extern __shared__ char sm[];
    const uint32_t smb = smem_u32(sm);
    __nv_bfloat16* Ahi = (__nv_bfloat16*)(sm + OFF_AHI);
    __nv_bfloat16* Alo = (__nv_bfloat16*)(sm + OFF_ALO);
    __nv_bfloat16* bxH = (__nv_bfloat16*)(sm + OFF_BXH);
    __nv_bfloat16* bxL = (__nv_bfloat16*)(sm + OFF_BXL);
    float* bboxS = (float*)(sm + OFF_BBOX);
    float* b1S   = (float*)(sm + OFF_B1);
    float* b2S   = (float*)(sm + OFF_B2);
    float* bs1S  = (float*)(sm + OFF_BS1);
    float* bmuS  = (float*)(sm + OFF_BMU);
    float* bvarS = (float*)(sm + OFF_BVAR);
    int*   semS  = (int*)(sm + OFF_SEM);
    int*   ncS   = (int*)(sm + OFF_NC);
    int*   permS = (int*)(sm + OFF_PERM);
    int*   maxncS = (int*)(sm + OFF_MAXNC);

    const int t = threadIdx.x;
    const int lane = t & 31;
    const int wid = t >> 5;
    const int wm = wid >> 2;      // 0..1 -> rows wm*16 + [0,16)
    const int wn = wid & 3;       // 0..3 -> cols wn*64 + [0,64)
    const int b0 = blockIdx.x * PT;

    // ---- stage constants + permuted per-parent data ----
    bboxS[t] = b_box[t];
    b1S[t]   = b1[t];
    b2S[t]   = b2[t];
    bs1S[t]  = bs1[t];
    bmuS[t]  = bmu[t];
    bvarS[t] = bvar[t];
    if (t < PT) {
        int pid = g_perm[b0 + t];
        permS[t] = pid;
        ncS[t] = n_children[pid];
    }
    __syncthreads();
    for (int i = t; i < PT * 10; i += NT) semS[i] = sem_ids[permS[i / 10] * 10 + (i % 10)];
    // stage box tiles as bf16 hi/lo in LDSM layout: [m][r][k], k padded to 16
    #pragma unroll 1
    for (int i = t; i < MAXC * PT * 16; i += NT) {
        int m = i >> 9;            // i / 512
        int rem = i & 511;
        int r = rem >> 4, k = rem & 15;
        float v = (k < 10) ? box_input[permS[r] * 100 + m * 10 + k] : 0.0f;
        __nv_bfloat16 h = __float2bfloat16(v);
        int idx = (m * PT + r) * BXSTR + k;
        bxH[idx] = h;
        bxL[idx] = __float2bfloat16(v - __bfloat162float(h));
    }
    if (t == 0) {
        int mx = 0;
        for (int i = 0; i < PT; i++) mx = max(mx, ncS[i]);
        maxncS[0] = mx;
    }
    __syncthreads();
    const int maxnc = maxncS[0];

    const int arow = (lane & 7) + ((lane >> 3) & 1) * 8;
    const int r_half0 = wm * 16 + (lane >> 2);
    const int colq = wn * 64 + (lane & 3) * 2;
    // box tile LDSM lane address (per child add m*1536)
    const uint32_t bxHiA = smb + OFF_BXH +
        (uint32_t)(((wm * 16 + arow) * BXSTR) * 2 + (lane >> 4) * 16);
    const uint32_t bxLoA = bxHiA + (OFF_BXL - OFF_BXH);
    const uint4* __restrict__ pbx = g_pkbox + (wn * 8) * 32 + lane;

    float C[8][4];
    float macc[8][4];
    #pragma unroll
    for (int nt = 0; nt < 8; nt++)
        #pragma unroll
        for (int q = 0; q < 4; q++) macc[nt][q] = 0.0f;

    // ---- children loop (bounded by block max nc), 2 barriers per child ----
    #pragma unroll 1
    for (int m = 0; m < maxnc; m++) {
        // leaf = relu(box @ Wbox + bbox) via ONE K=16 MMA pass
        {
            uint32_t ah[4], al[4];
            ldsm_x4(ah, bxHiA + m * (PT * BXSTR * 2));
            ldsm_x4(al, bxLoA + m * (PT * BXSTR * 2));
            uint4 B[8];
            #pragma unroll
            for (int nt = 0; nt < 8; nt++) B[nt] = pbx[nt * 32];
            #pragma unroll
            for (int nt = 0; nt < 8; nt++)
                #pragma unroll
                for (int q = 0; q < 4; q++) C[nt][q] = 0.0f;
            #pragma unroll
            for (int nt = 0; nt < 8; nt++) mma16816(C[nt], ah, B[nt].x, B[nt].y);
            #pragma unroll
            for (int nt = 0; nt < 8; nt++) mma16816(C[nt], al, B[nt].x, B[nt].y);
            #pragma unroll
            for (int nt = 0; nt < 8; nt++) mma16816(C[nt], ah, B[nt].z, B[nt].w);
            // epilogue: + bbox, relu, split into A
            #pragma unroll
            for (int half = 0; half < 2; half++) {
                int r = r_half0 + half * 8;
                #pragma unroll
                for (int nt = 0; nt < 8; nt++) {
                    int col = colq + nt * 8;
                    float2 bb = *(const float2*)&bboxS[col];
                    float v0 = fmaxf(C[nt][half * 2 + 0] + bb.x, 0.0f);
                    float v1 = fmaxf(C[nt][half * 2 + 1] + bb.y, 0.0f);
                    split_pair(Ahi, Alo, r * ASTR + col, v0, v1);
                }
            }
        }
        __syncthreads();   // A visible to all warps

        gemm_tc(smb, 0, lane, wm, wn, C);
        __syncthreads();   // all warps done reading A

        // epilogue in registers: macc = max(macc, relu(C + W1[256+sem] + b1))
        #pragma unroll
        for (int half = 0; half < 2; half++) {
            int r = r_half0 + half * 8;
            if (m < ncS[r]) {
                const float* wrow = W1 + ((256 + semS[r * 10 + m]) << 8);
                #pragma unroll
                for (int nt = 0; nt < 8; nt++) {
                    int col = colq + nt * 8;
                    float2 w  = *(const float2*)&wrow[col];
                    float2 bb = *(const float2*)&b1S[col];
                    macc[nt][half * 2 + 0] = fmaxf(macc[nt][half * 2 + 0],
                        fmaxf(C[nt][half * 2 + 0] + w.x + bb.x, 0.0f));
                    macc[nt][half * 2 + 1] = fmaxf(macc[nt][half * 2 + 1],
                        fmaxf(C[nt][half * 2 + 1] + w.y + bb.y, 0.0f));
                }
            }
        }
    }

    #define FRAGS_TO_A(SRC, BIAS, RELU)                                        \
        do {                                                                   \
            _Pragma("unroll")                                                  \
            for (int half = 0; half < 2; half++) {                             \
                int r = r_half0 + half * 8;                                    \
                _Pragma("unroll")                                              \
                for (int nt = 0; nt < 8; nt++) {                               \
                    int col = colq + nt * 8;                                   \
                    float2 bb = *(const float2*)&(BIAS)[col];                  \
                    float v0 = (SRC)[nt][half * 2 + 0] + bb.x;                 \
                    float v1 = (SRC)[nt][half * 2 + 1] + bb.y;                 \
                    if (RELU) { v0 = fmaxf(v0, 0.0f); v1 = fmaxf(v1, 0.0f); }  \
                    split_pair(Ahi, Alo, r * ASTR + col, v0, v1);              \
                }                                                              \
            }                                                                  \
        } while (0)

    // ---- parent_feat = relu(X @ W2 + b2) ----
    #pragma unroll
    for (int half = 0; half < 2; half++) {
        int r = r_half0 + half * 8;
        #pragma unroll
        for (int nt = 0; nt < 8; nt++) {
            int col = colq + nt * 8;
            split_pair(Ahi, Alo, r * ASTR + col,
                       macc[nt][half * 2 + 0], macc[nt][half * 2 + 1]);
        }
    }
    __syncthreads();
    gemm_tc(smb, 1, lane, wm, wn, C);
    __syncthreads();
    FRAGS_TO_A(C, b2S, 1);
    __syncthreads();

    // ---- enc = relu(P @ Ws1 + bs1) ----
    gemm_tc(smb, 2, lane, wm, wn, C);
    __syncthreads();
    FRAGS_TO_A(C, bs1S, 1);
    __syncthreads();

    // ---- mu = enc @ Wmu + bmu (kept in regs; A holds enc) ----
    gemm_tc(smb, 3, lane, wm, wn, C);
    float mu[8][4];
    #pragma unroll
    for (int half = 0; half < 2; half++)
        #pragma unroll
        for (int nt = 0; nt < 8; nt++) {
            int col = colq + nt * 8;
            float2 bb = *(const float2*)&bmuS[col];
            mu[nt][half * 2 + 0] = C[nt][half * 2 + 0] + bb.x;
            mu[nt][half * 2 + 1] = C[nt][half * 2 + 1] + bb.y;
        }

    // ---- logvar = enc @ Wvar + bvar (A untouched since enc write) ----
    gemm_tc(smb, 4, lane, wm, wn, C);
    #pragma unroll
    for (int half = 0; half < 2; half++) {
        int r = r_half0 + half * 8;
        int pid = permS[r];
        #pragma unroll
        for (int nt = 0; nt < 8; nt++) {
            int col = colq + nt * 8;
            float2 bb = *(const float2*)&bvarS[col];
            float2 e  = *(const float2*)&eps[pid * 256 + col];
            float lvx = C[nt][half * 2 + 0] + bb.x;
            float lvy = C[nt][half * 2 + 1] + bb.y;
            float mvx = mu[nt][half * 2 + 0];
            float mvy = mu[nt][half * 2 + 1];
            float sdx = expf(0.5f * lvx);
            float sdy = expf(0.5f * lvy);
            float2 samp, kld;
            samp.x = e.x * sdx + mvx;
            samp.y = e.y * sdy + mvy;
            kld.x = 1.0f + lvx - mvx * mvx - sdx * sdx;
            kld.y = 1.0f + lvy - mvy * mvy - sdy * sdy;
            *(float2*)&out[pid * 512 + col]       = samp;
            *(float2*)&out[pid * 512 + 256 + col] = kld;
        }
    }
}

// ================= launch =================
extern "C" void kernel_launch(void* const* d_in, const int* in_sizes, int n_in,
                              void* d_out, int out_size)
{
    const float* box   = (const float*)d_in[0];
    const float* eps   = (const float*)d_in[1];
    const float* W_box = (const float*)d_in[2];
    const float* b_box = (const float*)d_in[3];
    const float* W1    = (const float*)d_in[4];
    const float* b1    = (const float*)d_in[5];
    const float* W2    = (const float*)d_in[6];
    const float* b2    = (const float*)d_in[7];
    const float* Ws1   = (const float*)d_in[8];
    const float* bs1   = (const float*)d_in[9];
    const float* Wmu   = (const float*)d_in[10];
    const float* bmu   = (const float*)d_in[11];
    const float* Wvar  = (const float*)d_in[12];
    const float* bvar  = (const float*)d_in[13];
    const int*   sem   = (const int*)d_in[14];
    const int*   nc    = (const int*)d_in[15];
    float* out = (float*)d_out;

    prep_pack<<<320, 256>>>(W1, W2, Ws1, Wmu, Wvar);
    prep_pack_box<<<4, 256>>>(W_box);
    sort_zero<<<1, 32>>>();
    sort_count<<<B_N / 256, 256>>>(nc);
    sort_scatter<<<B_N / 256, 256>>>(nc);

    cudaFuncSetAttribute(recenc_tc_kernel,
                         cudaFuncAttributeMaxDynamicSharedMemorySize, SMEM_SZ);
    recenc_tc_kernel<<<GRID, NT, SMEM_SZ>>>(
        box, eps, W_box, b_box, W1, b1, b2, bs1, bmu, bvar, sem, nc, out);
}

// round 16
// speedup vs baseline: 3.1678x; 1.0583x over previous
#include <cuda_runtime.h>
#include <cuda_bf16.h>
#include <cstdint>

// RecursiveEncoder — mma.sync bf16 3-term split + nc-sorted child skipping.
// R16: child-PAIR stacked GEMM (one B pass serves two children, C0/C1 accums,
//      macc in smem); paired tensor-core leaf; histogram sort_count.
//      PT=32/NT=256, 2 CTAs/SM, LPT order, packed-global B fragments.

#define NT    256
#define PT    32
#define GRID  1024
#define MAXC  10
#define B_N   32768

#define ASTR  264          // A row stride (bf16): conflict-free LDSM
#define BXSTR 24           // box tile row stride (bf16): 48B

// ---- smem offsets (bytes) ----
#define OFF_A0H   0          // 32*264*2 = 16896
#define OFF_A0L   16896
#define OFF_A1H   33792
#define OFF_A1L   50688      // -> 67584
#define OFF_MACC  67584      // 16*256*8 = 32768 -> 100352
#define OFF_BXH   100352     // 2*32*24*2 = 3072 -> 103424
#define OFF_BXL   103424     // -> 106496
#define OFF_BBOX  106496
#define OFF_B1    107520
#define OFF_B2    108544
#define OFF_BS1   109568
#define OFF_BMU   110592
#define OFF_BVAR  111616
#define OFF_SEM   112640     // 1280
#define OFF_NC    113920     // 128
#define OFF_PERM  114048     // 128
#define OFF_MAXNC 114176     // 16
#define SMEM_SZ   114192

// Packed B fragments: [layer][chunk c:16][ngroup:32][lane:32] uint4 =
//   (hi_k01, hi_k89, lo_k01, lo_k89), n = ng*8 + lane>>2, k0 = c*16+(lane&3)*2
__device__ uint4 g_pk[5 * 16384];
__device__ uint4 g_pkbox[1024];          // W_box fragments, K padded 10->16
__device__ int g_cnt[16];
__device__ int g_rank[B_N];
__device__ int g_perm[B_N];

static __device__ __forceinline__ uint32_t smem_u32(const void* p) {
    uint32_t a;
    asm("{ .reg .u64 t; cvta.to.shared.u64 t, %1; cvt.u32.u64 %0, t; }"
        : "=r"(a) : "l"(p));
    return a;
}
static __device__ __forceinline__ void mma16816(float d[4], const uint32_t a[4],
                                                uint32_t b0, uint32_t b1)
{
    asm volatile(
        "mma.sync.aligned.m16n8k16.row.col.f32.bf16.bf16.f32 "
        "{%0,%1,%2,%3}, {%4,%5,%6,%7}, {%8,%9}, {%0,%1,%2,%3};"
        : "+f"(d[0]), "+f"(d[1]), "+f"(d[2]), "+f"(d[3])
        : "r"(a[0]), "r"(a[1]), "r"(a[2]), "r"(a[3]), "r"(b0), "r"(b1));
}
static __device__ __forceinline__ void ldsm_x4(uint32_t r[4], uint32_t addr) {
    asm volatile("ldmatrix.sync.aligned.m8n8.x4.shared.b16 {%0,%1,%2,%3}, [%4];"
                 : "=r"(r[0]), "=r"(r[1]), "=r"(r[2]), "=r"(r[3]) : "r"(addr));
}

// ---- prep: pack transposed hi/lo split weights in fragment order (uint4) ----
__global__ void prep_pack(const float* __restrict__ W1, const float* __restrict__ W2,
                          const float* __restrict__ Ws1, const float* __restrict__ Wmu,
                          const float* __restrict__ Wvar)
{
    int idx = blockIdx.x * blockDim.x + threadIdx.x;   // 81920
    int lane = idx & 31;
    int ng   = (idx >> 5) & 31;
    int c    = (idx >> 10) & 15;
    int l    = idx >> 14;
    const float* src = (l == 0) ? W1 : (l == 1) ? W2 : (l == 2) ? Ws1 : (l == 3) ? Wmu : Wvar;
    int n  = ng * 8 + (lane >> 2);
    int kb = c * 16 + (lane & 3) * 2;
    float v0 = src[(kb + 0) * 256 + n];
    float v1 = src[(kb + 1) * 256 + n];
    float v2 = src[(kb + 8) * 256 + n];
    float v3 = src[(kb + 9) * 256 + n];
    __nv_bfloat162 h01 = __float22bfloat162_rn(make_float2(v0, v1));
    __nv_bfloat162 h23 = __float22bfloat162_rn(make_float2(v2, v3));
    float r0 = v0 - __bfloat162float(__low2bfloat16(h01));
    float r1 = v1 - __bfloat162float(__high2bfloat16(h01));
    float r2 = v2 - __bfloat162float(__low2bfloat16(h23));
    float r3 = v3 - __bfloat162float(__high2bfloat16(h23));
    __nv_bfloat162 l01 = __float22bfloat162_rn(make_float2(r0, r1));
    __nv_bfloat162 l23 = __float22bfloat162_rn(make_float2(r2, r3));
    g_pk[idx] = make_uint4(*(uint32_t*)&h01, *(uint32_t*)&h23,
                           *(uint32_t*)&l01, *(uint32_t*)&l23);
}
__global__ void prep_pack_box(const float* __restrict__ W_box)
{
    int idx = blockIdx.x * blockDim.x + threadIdx.x;   // 1024
    int lane = idx & 31;
    int ng   = idx >> 5;
    int n  = ng * 8 + (lane >> 2);
    int kb = (lane & 3) * 2;
    float v0 = (kb + 0 < 10) ? W_box[(kb + 0) * 256 + n] : 0.0f;
    float v1 = (kb + 1 < 10) ? W_box[(kb + 1) * 256 + n] : 0.0f;
    float v2 = (kb + 8 < 10) ? W_box[(kb + 8) * 256 + n] : 0.0f;
    float v3 = (kb + 9 < 10) ? W_box[(kb + 9) * 256 + n] : 0.0f;
    __nv_bfloat162 h01 = __float22bfloat162_rn(make_float2(v0, v1));
    __nv_bfloat162 h23 = __float22bfloat162_rn(make_float2(v2, v3));
    float r0 = v0 - __bfloat162float(__low2bfloat16(h01));
    float r1 = v1 - __bfloat162float(__high2bfloat16(h01));
    float r2 = v2 - __bfloat162float(__low2bfloat16(h23));
    float r3 = v3 - __bfloat162float(__high2bfloat16(h23));
    __nv_bfloat162 l01 = __float22bfloat162_rn(make_float2(r0, r1));
    __nv_bfloat162 l23 = __float22bfloat162_rn(make_float2(r2, r3));
    g_pkbox[idx] = make_uint4(*(uint32_t*)&h01, *(uint32_t*)&h23,
                              *(uint32_t*)&l01, *(uint32_t*)&l23);
}
__global__ void sort_zero() { if (threadIdx.x < 16) g_cnt[threadIdx.x] = 0; }
// histogram count: one global atomic per bucket per block
__global__ void sort_count(const int* __restrict__ nc) {
    __shared__ int hist[MAXC];
    __shared__ int base[MAXC];
    int t = threadIdx.x;
    if (t < MAXC) hist[t] = 0;
    __syncthreads();
    int i = blockIdx.x * blockDim.x + t;
    int b = nc[i] - 1;
    int lr = atomicAdd(&hist[b], 1);
    __syncthreads();
    if (t < MAXC) base[t] = (hist[t] > 0) ? atomicAdd(&g_cnt[t], hist[t]) : 0;
    __syncthreads();
    g_rank[i] = base[b] + lr;
}
// LPT: descending-nc order -> heavy blocks first
__global__ void sort_scatter(const int* __restrict__ nc) {
    int i = blockIdx.x * blockDim.x + threadIdx.x;
    if (i < B_N) {
        int b = nc[i] - 1;
        int base = 0;
        #pragma unroll
        for (int j = 0; j < MAXC; j++) base += (j > b) ? g_cnt[j] : 0;
        g_perm[base + g_rank[i]] = i;
    }
}

// ---- single-A GEMM (tail layers): C0[16 x 64 per warp] ----
static __device__ __forceinline__ void gemm_tc(uint32_t smb, int layer,
                                               int lane, int wm, int wn,
                                               float C[8][4])
{
    #pragma unroll
    for (int nt = 0; nt < 8; nt++)
        #pragma unroll
        for (int q = 0; q < 4; q++) C[nt][q] = 0.0f;

    const int arow = (lane & 7) + ((lane >> 3) & 1) * 8;
    const int akoff = (lane >> 4) * 8;
    uint32_t aHi = smb + OFF_A0H + (uint32_t)(((wm * 16 + arow) * ASTR + akoff) * 2);
    uint32_t aLo = aHi + (OFF_A0L - OFF_A0H);

    const uint4* __restrict__ bp = g_pk + layer * 16384 + (wn * 8) * 32 + lane;

    #pragma unroll 1
    for (int c = 0; c < 16; c++) {
        uint4 B[8];
        #pragma unroll
        for (int nt = 0; nt < 8; nt++) B[nt] = bp[c * 1024 + nt * 32];
        uint32_t ah[4], al[4];
        ldsm_x4(ah, aHi + c * 32);
        ldsm_x4(al, aLo + c * 32);
        #pragma unroll
        for (int nt = 0; nt < 8; nt++) mma16816(C[nt], ah, B[nt].x, B[nt].y);
        #pragma unroll
        for (int nt = 0; nt < 8; nt++) mma16816(C[nt], al, B[nt].x, B[nt].y);
        #pragma unroll
        for (int nt = 0; nt < 8; nt++) mma16816(C[nt], ah, B[nt].z, B[nt].w);
    }
}

// ---- paired GEMM: one B pass, two A tiles, two accumulators ----
static __device__ __forceinline__ void gemm_tc2(uint32_t smb, int layer,
                                                int lane, int wm, int wn,
                                                float C0[8][4], float C1[8][4])
{
    #pragma unroll
    for (int nt = 0; nt < 8; nt++)
        #pragma unroll
        for (int q = 0; q < 4; q++) { C0[nt][q] = 0.0f; C1[nt][q] = 0.0f; }

    const int arow = (lane & 7) + ((lane >> 3) & 1) * 8;
    const int akoff = (lane >> 4) * 8;
    uint32_t a0 = smb + OFF_A0H + (uint32_t)(((wm * 16 + arow) * ASTR + akoff) * 2);

    const uint4* __restrict__ bp = g_pk + layer * 16384 + (wn * 8) * 32 + lane;

    #pragma unroll 1
    for (int c = 0; c < 16; c++) {
        uint4 B[8];
        #pragma unroll
        for (int nt = 0; nt < 8; nt++) B[nt] = bp[c * 1024 + nt * 32];
        uint32_t ah0[4], al0[4], ah1[4], al1[4];
        ldsm_x4(ah0, a0 + c * 32);
        ldsm_x4(al0, a0 + c * 32 + (OFF_A0L - OFF_A0H));
        ldsm_x4(ah1, a0 + c * 32 + (OFF_A1H - OFF_A0H));
        ldsm_x4(al1, a0 + c * 32 + (OFF_A1L - OFF_A0H));
        #pragma unroll
        for (int nt = 0; nt < 8; nt++) mma16816(C0[nt], ah0, B[nt].x, B[nt].y);
        #pragma unroll
        for (int nt = 0; nt < 8; nt++) mma16816(C1[nt], ah1, B[nt].x, B[nt].y);
        #pragma unroll
        for (int nt = 0; nt < 8; nt++) mma16816(C0[nt], al0, B[nt].x, B[nt].y);
        #pragma unroll
        for (int nt = 0; nt < 8; nt++) mma16816(C1[nt], al1, B[nt].x, B[nt].y);
        #pragma unroll
        for (int nt = 0; nt < 8; nt++) mma16816(C0[nt], ah0, B[nt].z, B[nt].w);
        #pragma unroll
        for (int nt = 0; nt < 8; nt++) mma16816(C1[nt], ah1, B[nt].z, B[nt].w);
    }
}

static __device__ __forceinline__ void split_pair(__nv_bfloat16* Ahi, __nv_bfloat16* Alo,
                                                  int idx, float s0, float s1)
{
    __nv_bfloat162 h2 = __float22bfloat162_rn(make_float2(s0, s1));
    float r0 = s0 - __bfloat162float(__low2bfloat16(h2));
    float r1 = s1 - __bfloat162float(__high2bfloat16(h2));
    __nv_bfloat162 l2 = __float22bfloat162_rn(make_float2(r0, r1));
    *(uint32_t*)&Ahi[idx] = *(uint32_t*)&h2;
    *(uint32_t*)&Alo[idx] = *(uint32_t*)&l2;
}

__global__ void __launch_bounds__(NT, 2)
recenc_tc_kernel(const float* __restrict__ box_input,
                 const float* __restrict__ eps,
                 const float* __restrict__ W_box,
                 const float* __restrict__ b_box,
                 const float* __restrict__ W1,
                 const float* __restrict__ b1,
                 const float* __restrict__ b2,
                 const float* __restrict__ bs1,
                 const float* __restrict__ bmu,
                 const float* __restrict__ bvar,
                 const int*   __restrict__ sem_ids,
                 const int*   __restrict__ n_children,
                 float*       __restrict__ out)
{
    extern __shared__ char sm[];
    const uint32_t smb = smem_u32(sm);
    __nv_bfloat16* A0h = (__nv_bfloat16*)(sm + OFF_A0H);
    __nv_bfloat16* A0l = (__nv_bfloat16*)(sm + OFF_A0L);
    __nv_bfloat16* A1h = (__nv_bfloat16*)(sm + OFF_A1H);
    __nv_bfloat16* A1l = (__nv_bfloat16*)(sm + OFF_A1L);
    float2* maccS2 = (float2*)(sm + OFF_MACC);     // [j:16][t:256]
    __nv_bfloat16* bxH = (__nv_bfloat16*)(sm + OFF_BXH);
    __nv_bfloat16* bxL = (__nv_bfloat16*)(sm + OFF_BXL);
    float* bboxS = (float*)(sm + OFF_BBOX);
    float* b1S   = (float*)(sm + OFF_B1);
    float* b2S   = (float*)(sm + OFF_B2);
    float* bs1S  = (float*)(sm + OFF_BS1);
    float* bmuS  = (float*)(sm + OFF_BMU);
    float* bvarS = (float*)(sm + OFF_BVAR);
    int*   semS  = (int*)(sm + OFF_SEM);
    int*   ncS   = (int*)(sm + OFF_NC);
    int*   permS = (int*)(sm + OFF_PERM);
    int*   maxncS = (int*)(sm + OFF_MAXNC);

    const int t = threadIdx.x;
    const int lane = t & 31;
    const int wid = t >> 5;
    const int wm = wid >> 2;      // 0..1 -> rows wm*16 + [0,16)
    const int wn = wid & 3;       // 0..3 -> cols wn*64 + [0,64)
    const int b0 = blockIdx.x * PT;

    // ---- stage constants + permuted per-parent data; zero macc ----
    bboxS[t] = b_box[t];
    b1S[t]   = b1[t];
    b2S[t]   = b2[t];
    bs1S[t]  = bs1[t];
    bmuS[t]  = bmu[t];
    bvarS[t] = bvar[t];
    if (t < PT) {
        int pid = g_perm[b0 + t];
        permS[t] = pid;
        ncS[t] = n_children[pid];
    }
    #pragma unroll
    for (int j = 0; j < 16; j++) maccS2[j * NT + t] = make_float2(0.0f, 0.0f);
    __syncthreads();
    for (int i = t; i < PT * 10; i += NT) semS[i] = sem_ids[permS[i / 10] * 10 + (i % 10)];
    if (t == 0) {
        int mx = 0;
        for (int i = 0; i < PT; i++) mx = max(mx, ncS[i]);
        maxncS[0] = mx;
    }
    __syncthreads();
    const int maxnc = maxncS[0];

    const int arow = (lane & 7) + ((lane >> 3) & 1) * 8;
    const int r_half0 = wm * 16 + (lane >> 2);
    const int colq = wn * 64 + (lane & 3) * 2;
    const uint32_t bxA = smb + OFF_BXH +
        (uint32_t)(((wm * 16 + arow) * BXSTR) * 2 + (lane >> 4) * 16);
    const uint4* __restrict__ pbx = g_pkbox + (wn * 8) * 32 + lane;

    float C0[8][4], C1[8][4];

    // ---- child-pair loop ----
    #pragma unroll 1
    for (int m = 0; m < maxnc; m += 2) {
        // stage this pair's box tiles (hi/lo, k padded to 16)
        #pragma unroll 1
        for (int i = t; i < 2 * PT * 16; i += NT) {
            int mm = i >> 9;
            int rem = i & 511;
            int r = rem >> 4, k = rem & 15;
            int mg = m + mm;
            float v = (k < 10 && mg < MAXC)
                      ? box_input[permS[r] * 100 + mg * 10 + k] : 0.0f;
            __nv_bfloat16 h = __float2bfloat16(v);
            int idx = (mm * PT + r) * BXSTR + k;
            bxH[idx] = h;
            bxL[idx] = __float2bfloat16(v - __bfloat162float(h));
        }
        __syncthreads();   // box tiles visible; previous gemm2 readers long done

        // paired leaf: one B load, both children -> A0, A1
        {
            uint32_t ah0[4], al0[4], ah1[4], al1[4];
            ldsm_x4(ah0, bxA);
            ldsm_x4(al0, bxA + (OFF_BXL - OFF_BXH));
            ldsm_x4(ah1, bxA + PT * BXSTR * 2);
            ldsm_x4(al1, bxA + (OFF_BXL - OFF_BXH) + PT * BXSTR * 2);
            uint4 B[8];
            #pragma unroll
            for (int nt = 0; nt < 8; nt++) B[nt] = pbx[nt * 32];
            #pragma unroll
            for (int nt = 0; nt < 8; nt++)
                #pragma unroll
                for (int q = 0; q < 4; q++) { C0[nt][q] = 0.0f; C1[nt][q] = 0.0f; }
            #pragma unroll
            for (int nt = 0; nt < 8; nt++) mma16816(C0[nt], ah0, B[nt].x, B[nt].y);
            #pragma unroll
            for (int nt = 0; nt < 8; nt++) mma16816(C1[nt], ah1, B[nt].x, B[nt].y);
            #pragma unroll
            for (int nt = 0; nt < 8; nt++) mma16816(C0[nt], al0, B[nt].x, B[nt].y);
            #pragma unroll
            for (int nt = 0; nt < 8; nt++) mma16816(C1[nt], al1, B[nt].x, B[nt].y);
            #pragma unroll
            for (int nt = 0; nt < 8; nt++) mma16816(C0[nt], ah0, B[nt].z, B[nt].w);
            #pragma unroll
            for (int nt = 0; nt < 8; nt++) mma16816(C1[nt], ah1, B[nt].z, B[nt].w);
            // epilogue both: + bbox, relu, split into A0/A1
            #pragma unroll
            for (int half = 0; half < 2; half++) {
                int r = r_half0 + half * 8;
                #pragma unroll
                for (int nt = 0; nt < 8; nt++) {
                    int col = colq + nt * 8;
                    float2 bb = *(const float2*)&bboxS[col];
                    split_pair(A0h, A0l, r * ASTR + col,
                               fmaxf(C0[nt][half * 2 + 0] + bb.x, 0.0f),
                               fmaxf(C0[nt][half * 2 + 1] + bb.y, 0.0f));
                    split_pair(A1h, A1l, r * ASTR + col,
                               fmaxf(C1[nt][half * 2 + 0] + bb.x, 0.0f),
                               fmaxf(C1[nt][half * 2 + 1] + bb.y, 0.0f));
                }
            }
        }
        __syncthreads();   // A0/A1 visible

        gemm_tc2(smb, 0, lane, wm, wn, C0, C1);
        __syncthreads();   // all warps done reading A0/A1

        // epilogues: macc (smem, thread-exclusive) = max(macc, relu(C + W1row + b1))
        #pragma unroll
        for (int cc = 0; cc < 2; cc++) {
            int mm = m + cc;
            if (mm >= maxnc) break;
            #pragma unroll
            for (int half = 0; half < 2; half++) {
                int r = r_half0 + half * 8;
                if (mm < ncS[r]) {
                    const float* wrow = W1 + ((256 + semS[r * 10 + mm]) << 8);
                    #pragma unroll
                    for (int nt = 0; nt < 8; nt++) {
                        int col = colq + nt * 8;
                        float2 w  = *(const float2*)&wrow[col];
                        float2 bb = *(const float2*)&b1S[col];
                        float cv0 = cc ? C1[nt][half * 2 + 0] : C0[nt][half * 2 + 0];
                        float cv1 = cc ? C1[nt][half * 2 + 1] : C0[nt][half * 2 + 1];
                        int j = half * 8 + nt;
                        float2 mo = maccS2[j * NT + t];
                        mo.x = fmaxf(mo.x, fmaxf(cv0 + w.x + bb.x, 0.0f));
                        mo.y = fmaxf(mo.y, fmaxf(cv1 + w.y + bb.y, 0.0f));
                        maccS2[j * NT + t] = mo;
                    }
                }
            }
        }
    }

    #define FRAGS_TO_A(SRC, BIAS, RELU)                                        \
        do {                                                                   \
            _Pragma("unroll")                                                  \
            for (int half = 0; half < 2; half++) {                             \
                int r = r_half0 + half * 8;                                    \
                _Pragma("unroll")                                              \
                for (int nt = 0; nt < 8; nt++) {                               \
                    int col = colq + nt * 8;                                   \
                    float2 bb = *(const float2*)&(BIAS)[col];                  \
                    float v0 = (SRC)[nt][half * 2 + 0] + bb.x;                 \
                    float v1 = (SRC)[nt][half * 2 + 1] + bb.y;                 \
                    if (RELU) { v0 = fmaxf(v0, 0.0f); v1 = fmaxf(v1, 0.0f); }  \
                    split_pair(A0h, A0l, r * ASTR + col, v0, v1);              \
                }                                                              \
            }                                                                  \
        } while (0)

    // ---- X (= macc) -> A0 ----
    #pragma unroll
    for (int half = 0; half < 2; half++) {
        int r = r_half0 + half * 8;
        #pragma unroll
        for (int nt = 0; nt < 8; nt++) {
            int col = colq + nt * 8;
            float2 v = maccS2[(half * 8 + nt) * NT + t];
            split_pair(A0h, A0l, r * ASTR + col, v.x, v.y);
        }
    }
    __syncthreads();

    // ---- parent_feat = relu(X @ W2 + b2) ----
    gemm_tc(smb, 1, lane, wm, wn, C0);
    __syncthreads();
    FRAGS_TO_A(C0, b2S, 1);
    __syncthreads();

    // ---- enc = relu(P @ Ws1 + bs1) ----
    gemm_tc(smb, 2, lane, wm, wn, C0);
    __syncthreads();
    FRAGS_TO_A(C0, bs1S, 1);
    __syncthreads();

    // ---- mu = enc @ Wmu + bmu (regs; A0 holds enc) ----
    gemm_tc(smb, 3, lane, wm, wn, C0);
    float mu[8][4];
    #pragma unroll
    for (int half = 0; half < 2; half++)
        #pragma unroll
        for (int nt = 0; nt < 8; nt++) {
            int col = colq + nt * 8;
            float2 bb = *(const float2*)&bmuS[col];
            mu[nt][half * 2 + 0] = C0[nt][half * 2 + 0] + bb.x;
            mu[nt][half * 2 + 1] = C0[nt][half * 2 + 1] + bb.y;
        }

    // ---- logvar = enc @ Wvar + bvar (A0 untouched); sampler epilogue ----
    gemm_tc(smb, 4, lane, wm, wn, C0);
    #pragma unroll
    for (int half = 0; half < 2; half++) {
        int r = r_half0 + half * 8;
        int pid = permS[r];
        #pragma unroll
        for (int nt = 0; nt < 8; nt++) {
            int col = colq + nt * 8;
            float2 bb = *(const float2*)&bvarS[col];
            float2 e  = *(const float2*)&eps[pid * 256 + col];
            float lvx = C0[nt][half * 2 + 0] + bb.x;
            float lvy = C0[nt][half * 2 + 1] + bb.y;
            float mvx = mu[nt][half * 2 + 0];
            float mvy = mu[nt][half * 2 + 1];
            float sdx = expf(0.5f * lvx);
            float sdy = expf(0.5f * lvy);
            float2 samp, kld;
            samp.x = e.x * sdx + mvx;
            samp.y = e.y * sdy + mvy;
            kld.x = 1.0f + lvx - mvx * mvx - sdx * sdx;
            kld.y = 1.0f + lvy - mvy * mvy - sdy * sdy;
            *(float2*)&out[pid * 512 + col]       = samp;
            *(float2*)&out[pid * 512 + 256 + col] = kld;
        }
    }
}

// ================= launch =================
extern "C" void kernel_launch(void* const* d_in, const int* in_sizes, int n_in,
                              void* d_out, int out_size)
{
    const float* box   = (const float*)d_in[0];
    const float* eps   = (const float*)d_in[1];
    const float* W_box = (const float*)d_in[2];
    const float* b_box = (const float*)d_in[3];
    const float* W1    = (const float*)d_in[4];
    const float* b1    = (const float*)d_in[5];
    const float* W2    = (const float*)d_in[6];
    const float* b2    = (const float*)d_in[7];
    const float* Ws1   = (const float*)d_in[8];
    const float* bs1   = (const float*)d_in[9];
    const float* Wmu   = (const float*)d_in[10];
    const float* bmu   = (const float*)d_in[11];
    const float* Wvar  = (const float*)d_in[12];
    const float* bvar  = (const float*)d_in[13];
    const int*   sem   = (const int*)d_in[14];
    const int*   nc    = (const int*)d_in[15];
    float* out = (float*)d_out;

    prep_pack<<<320, 256>>>(W1, W2, Ws1, Wmu, Wvar);
    prep_pack_box<<<4, 256>>>(W_box);
    sort_zero<<<1, 32>>>();
    sort_count<<<B_N / 256, 256>>>(nc);
    sort_scatter<<<B_N / 256, 256>>>(nc);

    cudaFuncSetAttribute(recenc_tc_kernel,
                         cudaFuncAttributeMaxDynamicSharedMemorySize, SMEM_SZ);
    recenc_tc_kernel<<<GRID, NT, SMEM_SZ>>>(
        box, eps, W_box, b_box, W1, b1, b2, bs1, bmu, bvar, sem, nc, out);
}

// round 17
// speedup vs baseline: 3.3454x; 1.0561x over previous
#include <cuda_runtime.h>
#include <cuda_bf16.h>
#include <cstdint>

// RecursiveEncoder — mma.sync bf16 3-term split + nc-sorted child skipping.
// R17: warp-unique wn layout (8 warps x N=32, M=32 each) -> every B fragment
//      loaded exactly once per CTA. Child pairing, smem macc, tensor leaf,
//      PT=32/NT=256, 2 CTAs/SM, LPT order.

#define NT    256
#define PT    32
#define GRID  1024
#define MAXC  10
#define B_N   32768

#define ASTR  264          // A row stride (bf16): conflict-free LDSM
#define BXSTR 24           // box tile row stride (bf16): 48B

// ---- smem offsets (bytes) ----
#define OFF_A0H   0          // 32*264*2 = 16896
#define OFF_A0L   16896
#define OFF_A1H   33792
#define OFF_A1L   50688      // -> 67584
#define OFF_MACC  67584      // 16*256*8 = 32768 -> 100352
#define OFF_BXH   100352     // 2*32*24*2 = 3072
#define OFF_BXL   103424
#define OFF_BBOX  106496
#define OFF_B1    107520
#define OFF_B2    108544
#define OFF_BS1   109568
#define OFF_BMU   110592
#define OFF_BVAR  111616
#define OFF_SEM   112640     // 1280
#define OFF_NC    113920     // 128
#define OFF_PERM  114048     // 128
#define OFF_MAXNC 114176     // 16
#define SMEM_SZ   114192

// Packed B fragments: [layer][chunk c:16][ngroup:32][lane:32] uint4 =
//   (hi_k01, hi_k89, lo_k01, lo_k89), n = ng*8 + lane>>2, k0 = c*16+(lane&3)*2
__device__ uint4 g_pk[5 * 16384];
__device__ uint4 g_pkbox[1024];          // W_box fragments, K padded 10->16
__device__ int g_cnt[16];
__device__ int g_rank[B_N];
__device__ int g_perm[B_N];

static __device__ __forceinline__ uint32_t smem_u32(const void* p) {
    uint32_t a;
    asm("{ .reg .u64 t; cvta.to.shared.u64 t, %1; cvt.u32.u64 %0, t; }"
        : "=r"(a) : "l"(p));
    return a;
}
static __device__ __forceinline__ void mma16816(float d[4], const uint32_t a[4],
                                                uint32_t b0, uint32_t b1)
{
    asm volatile(
        "mma.sync.aligned.m16n8k16.row.col.f32.bf16.bf16.f32 "
        "{%0,%1,%2,%3}, {%4,%5,%6,%7}, {%8,%9}, {%0,%1,%2,%3};"
        : "+f"(d[0]), "+f"(d[1]), "+f"(d[2]), "+f"(d[3])
        : "r"(a[0]), "r"(a[1]), "r"(a[2]), "r"(a[3]), "r"(b0), "r"(b1));
}
static __device__ __forceinline__ void ldsm_x4(uint32_t r[4], uint32_t addr) {
    asm volatile("ldmatrix.sync.aligned.m8n8.x4.shared.b16 {%0,%1,%2,%3}, [%4];"
                 : "=r"(r[0]), "=r"(r[1]), "=r"(r[2]), "=r"(r[3]) : "r"(addr));
}

// ---- prep: pack transposed hi/lo split weights in fragment order (uint4) ----
__global__ void prep_pack(const float* __restrict__ W1, const float* __restrict__ W2,
                          const float* __restrict__ Ws1, const float* __restrict__ Wmu,
                          const float* __restrict__ Wvar)
{
    int idx = blockIdx.x * blockDim.x + threadIdx.x;   // 81920
    if (idx < 16) g_cnt[idx] = 0;                      // folded sort_zero
    int lane = idx & 31;
    int ng   = (idx >> 5) & 31;
    int c    = (idx >> 10) & 15;
    int l    = idx >> 14;
    const float* src = (l == 0) ? W1 : (l == 1) ? W2 : (l == 2) ? Ws1 : (l == 3) ? Wmu : Wvar;
    int n  = ng * 8 + (lane >> 2);
    int kb = c * 16 + (lane & 3) * 2;
    float v0 = src[(kb + 0) * 256 + n];
    float v1 = src[(kb + 1) * 256 + n];
    float v2 = src[(kb + 8) * 256 + n];
    float v3 = src[(kb + 9) * 256 + n];
    __nv_bfloat162 h01 = __float22bfloat162_rn(make_float2(v0, v1));
    __nv_bfloat162 h23 = __float22bfloat162_rn(make_float2(v2, v3));
    float r0 = v0 - __bfloat162float(__low2bfloat16(h01));
    float r1 = v1 - __bfloat162float(__high2bfloat16(h01));
    float r2 = v2 - __bfloat162float(__low2bfloat16(h23));
    float r3 = v3 - __bfloat162float(__high2bfloat16(h23));
    __nv_bfloat162 l01 = __float22bfloat162_rn(make_float2(r0, r1));
    __nv_bfloat162 l23 = __float22bfloat162_rn(make_float2(r2, r3));
    g_pk[idx] = make_uint4(*(uint32_t*)&h01, *(uint32_t*)&h23,
                           *(uint32_t*)&l01, *(uint32_t*)&l23);
}
__global__ void prep_pack_box(const float* __restrict__ W_box)
{
    int idx = blockIdx.x * blockDim.x + threadIdx.x;   // 1024
    int lane = idx & 31;
    int ng   = idx >> 5;
    int n  = ng * 8 + (lane >> 2);
    int kb = (lane & 3) * 2;
    float v0 = (kb + 0 < 10) ? W_box[(kb + 0) * 256 + n] : 0.0f;
    float v1 = (kb + 1 < 10) ? W_box[(kb + 1) * 256 + n] : 0.0f;
    float v2 = (kb + 8 < 10) ? W_box[(kb + 8) * 256 + n] : 0.0f;
    float v3 = (kb + 9 < 10) ? W_box[(kb + 9) * 256 + n] : 0.0f;
    __nv_bfloat162 h01 = __float22bfloat162_rn(make_float2(v0, v1));
    __nv_bfloat162 h23 = __float22bfloat162_rn(make_float2(v2, v3));
    float r0 = v0 - __bfloat162float(__low2bfloat16(h01));
    float r1 = v1 - __bfloat162float(__high2bfloat16(h01));
    float r2 = v2 - __bfloat162float(__low2bfloat16(h23));
    float r3 = v3 - __bfloat162float(__high2bfloat16(h23));
    __nv_bfloat162 l01 = __float22bfloat162_rn(make_float2(r0, r1));
    __nv_bfloat162 l23 = __float22bfloat162_rn(make_float2(r2, r3));
    g_pkbox[idx] = make_uint4(*(uint32_t*)&h01, *(uint32_t*)&h23,
                              *(uint32_t*)&l01, *(uint32_t*)&l23);
}
// histogram count: one global atomic per bucket per block
__global__ void sort_count(const int* __restrict__ nc) {
    __shared__ int hist[MAXC];
    __shared__ int base[MAXC];
    int t = threadIdx.x;
    if (t < MAXC) hist[t] = 0;
    __syncthreads();
    int i = blockIdx.x * blockDim.x + t;
    int b = nc[i] - 1;
    int lr = atomicAdd(&hist[b], 1);
    __syncthreads();
    if (t < MAXC) base[t] = (hist[t] > 0) ? atomicAdd(&g_cnt[t], hist[t]) : 0;
    __syncthreads();
    g_rank[i] = base[b] + lr;
}
// LPT: descending-nc order -> heavy blocks first
__global__ void sort_scatter(const int* __restrict__ nc) {
    int i = blockIdx.x * blockDim.x + threadIdx.x;
    if (i < B_N) {
        int b = nc[i] - 1;
        int base = 0;
        #pragma unroll
        for (int j = 0; j < MAXC; j++) base += (j > b) ? g_cnt[j] : 0;
        g_perm[base + g_rank[i]] = i;
    }
}

// ---- single-A GEMM: C[2 mtiles][4 nt][4], m-tiles interleaved (dep dist 8) ----
static __device__ __forceinline__ void gemm_tc(uint32_t smb, int layer,
                                               int lane, int wn,
                                               float C[2][4][4])
{
    #pragma unroll
    for (int mt = 0; mt < 2; mt++)
        #pragma unroll
        for (int nt = 0; nt < 4; nt++)
            #pragma unroll
            for (int q = 0; q < 4; q++) C[mt][nt][q] = 0.0f;

    const int arow = (lane & 7) + ((lane >> 3) & 1) * 8;
    const int akoff = (lane >> 4) * 8;
    uint32_t a0 = smb + OFF_A0H + (uint32_t)((arow * ASTR + akoff) * 2);

    const uint4* __restrict__ bp = g_pk + layer * 16384 + (wn * 4) * 32 + lane;

    #pragma unroll 1
    for (int c = 0; c < 16; c++) {
        uint4 B[4];
        #pragma unroll
        for (int nt = 0; nt < 4; nt++) B[nt] = bp[c * 1024 + nt * 32];
        uint32_t ah[2][4], al[2][4];
        #pragma unroll
        for (int mt = 0; mt < 2; mt++) {
            ldsm_x4(ah[mt], a0 + mt * (16 * ASTR * 2) + c * 32);
            ldsm_x4(al[mt], a0 + mt * (16 * ASTR * 2) + c * 32 + (OFF_A0L - OFF_A0H));
        }
        #pragma unroll
        for (int mt = 0; mt < 2; mt++)
            #pragma unroll
            for (int nt = 0; nt < 4; nt++) mma16816(C[mt][nt], ah[mt], B[nt].x, B[nt].y);
        #pragma unroll
        for (int mt = 0; mt < 2; mt++)
            #pragma unroll
            for (int nt = 0; nt < 4; nt++) mma16816(C[mt][nt], al[mt], B[nt].x, B[nt].y);
        #pragma unroll
        for (int mt = 0; mt < 2; mt++)
            #pragma unroll
            for (int nt = 0; nt < 4; nt++) mma16816(C[mt][nt], ah[mt], B[nt].z, B[nt].w);
    }
}

// ---- paired GEMM: two A tiles (children), children interleaved per m-tile ----
static __device__ __forceinline__ void gemm_tc2(uint32_t smb, int layer,
                                                int lane, int wn,
                                                float C0[2][4][4], float C1[2][4][4])
{
    #pragma unroll
    for (int mt = 0; mt < 2; mt++)
        #pragma unroll
        for (int nt = 0; nt < 4; nt++)
            #pragma unroll
            for (int q = 0; q < 4; q++) { C0[mt][nt][q] = 0.0f; C1[mt][nt][q] = 0.0f; }

    const int arow = (lane & 7) + ((lane >> 3) & 1) * 8;
    const int akoff = (lane >> 4) * 8;
    uint32_t a0 = smb + OFF_A0H + (uint32_t)((arow * ASTR + akoff) * 2);

    const uint4* __restrict__ bp = g_pk + layer * 16384 + (wn * 4) * 32 + lane;

    #pragma unroll 1
    for (int c = 0; c < 16; c++) {
        uint4 B[4];
        #pragma unroll
        for (int nt = 0; nt < 4; nt++) B[nt] = bp[c * 1024 + nt * 32];
        #pragma unroll
        for (int mt = 0; mt < 2; mt++) {
            uint32_t base = a0 + mt * (16 * ASTR * 2) + c * 32;
            uint32_t ah0[4], al0[4], ah1[4], al1[4];
            ldsm_x4(ah0, base);
            ldsm_x4(al0, base + (OFF_A0L - OFF_A0H));
            ldsm_x4(ah1, base + (OFF_A1H - OFF_A0H));
            ldsm_x4(al1, base + (OFF_A1L - OFF_A0H));
            // term-major, children interleaved: dep distance 8
            #pragma unroll
            for (int nt = 0; nt < 4; nt++) mma16816(C0[mt][nt], ah0, B[nt].x, B[nt].y);
            #pragma unroll
            for (int nt = 0; nt < 4; nt++) mma16816(C1[mt][nt], ah1, B[nt].x, B[nt].y);
            #pragma unroll
            for (int nt = 0; nt < 4; nt++) mma16816(C0[mt][nt], al0, B[nt].x, B[nt].y);
            #pragma unroll
            for (int nt = 0; nt < 4; nt++) mma16816(C1[mt][nt], al1, B[nt].x, B[nt].y);
            #pragma unroll
            for (int nt = 0; nt < 4; nt++) mma16816(C0[mt][nt], ah0, B[nt].z, B[nt].w);
            #pragma unroll
            for (int nt = 0; nt < 4; nt++) mma16816(C1[mt][nt], ah1, B[nt].z, B[nt].w);
        }
    }
}

static __device__ __forceinline__ void split_pair(__nv_bfloat16* Ahi, __nv_bfloat16* Alo,
                                                  int idx, float s0, float s1)
{
    __nv_bfloat162 h2 = __float22bfloat162_rn(make_float2(s0, s1));
    float r0 = s0 - __bfloat162float(__low2bfloat16(h2));
    float r1 = s1 - __bfloat162float(__high2bfloat16(h2));
    __nv_bfloat162 l2 = __float22bfloat162_rn(make_float2(r0, r1));
    *(uint32_t*)&Ahi[idx] = *(uint32_t*)&h2;
    *(uint32_t*)&Alo[idx] = *(uint32_t*)&l2;
}

__global__ void __launch_bounds__(NT, 2)
recenc_tc_kernel(const float* __restrict__ box_input,
                 const float* __restrict__ eps,
                 const float* __restrict__ W_box,
                 const float* __restrict__ b_box,
                 const float* __restrict__ W1,
                 const float* __restrict__ b1,
                 const float* __restrict__ b2,
                 const float* __restrict__ bs1,
                 const float* __restrict__ bmu,
                 const float* __restrict__ bvar,
                 const int*   __restrict__ sem_ids,
                 const int*   __restrict__ n_children,
                 float*       __restrict__ out)
{
    extern __shared__ char sm[];
    const uint32_t smb = smem_u32(sm);
    __nv_bfloat16* A0h = (__nv_bfloat16*)(sm + OFF_A0H);
    __nv_bfloat16* A0l = (__nv_bfloat16*)(sm + OFF_A0L);
    __nv_bfloat16* A1h = (__nv_bfloat16*)(sm + OFF_A1H);
    __nv_bfloat16* A1l = (__nv_bfloat16*)(sm + OFF_A1L);
    float2* maccS2 = (float2*)(sm + OFF_MACC);     // [j:16][t:256]
    __nv_bfloat16* bxH = (__nv_bfloat16*)(sm + OFF_BXH);
    __nv_bfloat16* bxL = (__nv_bfloat16*)(sm + OFF_BXL);
    float* bboxS = (float*)(sm + OFF_BBOX);
    float* b1S   = (float*)(sm + OFF_B1);
    float* b2S   = (float*)(sm + OFF_B2);
    float* bs1S  = (float*)(sm + OFF_BS1);
    float* bmuS  = (float*)(sm + OFF_BMU);
    float* bvarS = (float*)(sm + OFF_BVAR);
    int*   semS  = (int*)(sm + OFF_SEM);
    int*   ncS   = (int*)(sm + OFF_NC);
    int*   permS = (int*)(sm + OFF_PERM);
    int*   maxncS = (int*)(sm + OFF_MAXNC);

    const int t = threadIdx.x;
    const int lane = t & 31;
    const int wn = t >> 5;        // 0..7 -> cols wn*32 + [0,32)
    const int b0 = blockIdx.x * PT;

    // ---- stage constants + permuted per-parent data; zero macc ----
    bboxS[t] = b_box[t];
    b1S[t]   = b1[t];
    b2S[t]   = b2[t];
    bs1S[t]  = bs1[t];
    bmuS[t]  = bmu[t];
    bvarS[t] = bvar[t];
    if (t < PT) {
        int pid = g_perm[b0 + t];
        permS[t] = pid;
        ncS[t] = n_children[pid];
    }
    #pragma unroll
    for (int j = 0; j < 16; j++) maccS2[j * NT + t] = make_float2(0.0f, 0.0f);
    __syncthreads();
    for (int i = t; i < PT * 10; i += NT) semS[i] = sem_ids[permS[i / 10] * 10 + (i % 10)];
    if (t == 0) {
        int mx = 0;
        for (int i = 0; i < PT; i++) mx = max(mx, ncS[i]);
        maxncS[0] = mx;
    }
    __syncthreads();
    const int maxnc = maxncS[0];

    const int arow = (lane & 7) + ((lane >> 3) & 1) * 8;
    const int r_q = (lane >> 2);           // row base within m-tile/half
    const int colq = wn * 32 + (lane & 3) * 2;
    const uint32_t bxA = smb + OFF_BXH +
        (uint32_t)((arow * BXSTR) * 2 + (lane >> 4) * 16);
    const uint4* __restrict__ pbx = g_pkbox + (wn * 4) * 32 + lane;

    float C0[2][4][4], C1[2][4][4];

    // ---- child-pair loop ----
    #pragma unroll 1
    for (int m = 0; m < maxnc; m += 2) {
        // stage this pair's box tiles (hi/lo, k padded to 16)
        #pragma unroll 1
        for (int i = t; i < 2 * PT * 16; i += NT) {
            int mm = i >> 9;
            int rem = i & 511;
            int r = rem >> 4, k = rem & 15;
            int mg = m + mm;
            float v = (k < 10 && mg < MAXC)
                      ? box_input[permS[r] * 100 + mg * 10 + k] : 0.0f;
            __nv_bfloat16 h = __float2bfloat16(v);
            int idx = (mm * PT + r) * BXSTR + k;
            bxH[idx] = h;
            bxL[idx] = __float2bfloat16(v - __bfloat162float(h));
        }
        __syncthreads();

        // paired leaf: one B load, both children, both m-tiles
        {
            uint4 B[4];
            #pragma unroll
            for (int nt = 0; nt < 4; nt++) B[nt] = pbx[nt * 32];
            #pragma unroll
            for (int mt = 0; mt < 2; mt++) {
                uint32_t base = bxA + mt * (16 * BXSTR * 2);
                uint32_t ah0[4], al0[4], ah1[4], al1[4];
                ldsm_x4(ah0, base);
                ldsm_x4(al0, base + (OFF_BXL - OFF_BXH));
                ldsm_x4(ah1, base + PT * BXSTR * 2);
                ldsm_x4(al1, base + (OFF_BXL - OFF_BXH) + PT * BXSTR * 2);
                #pragma unroll
                for (int nt = 0; nt < 4; nt++)
                    #pragma unroll
                    for (int q = 0; q < 4; q++) { C0[mt][nt][q] = 0.0f; C1[mt][nt][q] = 0.0f; }
                #pragma unroll
                for (int nt = 0; nt < 4; nt++) mma16816(C0[mt][nt], ah0, B[nt].x, B[nt].y);
                #pragma unroll
                for (int nt = 0; nt < 4; nt++) mma16816(C1[mt][nt], ah1, B[nt].x, B[nt].y);
                #pragma unroll
                for (int nt = 0; nt < 4; nt++) mma16816(C0[mt][nt], al0, B[nt].x, B[nt].y);
                #pragma unroll
                for (int nt = 0; nt < 4; nt++) mma16816(C1[mt][nt], al1, B[nt].x, B[nt].y);
                #pragma unroll
                for (int nt = 0; nt < 4; nt++) mma16816(C0[mt][nt], ah0, B[nt].z, B[nt].w);
                #pragma unroll
                for (int nt = 0; nt < 4; nt++) mma16816(C1[mt][nt], ah1, B[nt].z, B[nt].w);
            }
            // epilogue both children: + bbox, relu, split into A0/A1
            #pragma unroll
            for (int mt = 0; mt < 2; mt++)
                #pragma unroll
                for (int half = 0; half < 2; half++) {
                    int r = mt * 16 + r_q + half * 8;
                    #pragma unroll
                    for (int nt = 0; nt < 4; nt++) {
                        int col = colq + nt * 8;
                        float2 bb = *(const float2*)&bboxS[col];
                        split_pair(A0h, A0l, r * ASTR + col,
                                   fmaxf(C0[mt][nt][half * 2 + 0] + bb.x, 0.0f),
                                   fmaxf(C0[mt][nt][half * 2 + 1] + bb.y, 0.0f));
                        split_pair(A1h, A1l, r * ASTR + col,
                                   fmaxf(C1[mt][nt][half * 2 + 0] + bb.x, 0.0f),
                                   fmaxf(C1[mt][nt][half * 2 + 1] + bb.y, 0.0f));
                    }
                }
        }
        __syncthreads();   // A0/A1 visible

        gemm_tc2(smb, 0, lane, wn, C0, C1);
        __syncthreads();   // all warps done reading A0/A1

        // epilogues: macc (smem, thread-exclusive) = max(macc, relu(C + W1row + b1))
        #pragma unroll
        for (int cc = 0; cc < 2; cc++) {
            int mm = m + cc;
            if (mm >= maxnc) break;
            #pragma unroll
            for (int mt = 0; mt < 2; mt++)
                #pragma unroll
                for (int half = 0; half < 2; half++) {
                    int r = mt * 16 + r_q + half * 8;
                    if (mm < ncS[r]) {
                        const float* wrow = W1 + ((256 + semS[r * 10 + mm]) << 8);
                        #pragma unroll
                        for (int nt = 0; nt < 4; nt++) {
                            int col = colq + nt * 8;
                            float2 w  = *(const float2*)&wrow[col];
                            float2 bb = *(const float2*)&b1S[col];
                            float cv0 = cc ? C1[mt][nt][half * 2 + 0] : C0[mt][nt][half * 2 + 0];
                            float cv1 = cc ? C1[mt][nt][half * 2 + 1] : C0[mt][nt][half * 2 + 1];
                            int j = (mt * 2 + half) * 4 + nt;
                            float2 mo = maccS2[j * NT + t];
                            mo.x = fmaxf(mo.x, fmaxf(cv0 + w.x + bb.x, 0.0f));
                            mo.y = fmaxf(mo.y, fmaxf(cv1 + w.y + bb.y, 0.0f));
                            maccS2[j * NT + t] = mo;
                        }
                    }
                }
        }
    }

    #define FRAGS_TO_A(SRC, BIAS, RELU)                                        \
        do {                                                                   \
            _Pragma("unroll")                                                  \
            for (int mt = 0; mt < 2; mt++)                                     \
            _Pragma("unroll")                                                  \
            for (int half = 0; half < 2; half++) {                             \
                int r = mt * 16 + r_q + half * 8;                              \
                _Pragma("unroll")                                              \
                for (int nt = 0; nt < 4; nt++) {                               \
                    int col = colq + nt * 8;                                   \
                    float2 bb = *(const float2*)&(BIAS)[col];                  \
                    float v0 = (SRC)[mt][nt][half * 2 + 0] + bb.x;             \
                    float v1 = (SRC)[mt][nt][half * 2 + 1] + bb.y;             \
                    if (RELU) { v0 = fmaxf(v0, 0.0f); v1 = fmaxf(v1, 0.0f); }  \
                    split_pair(A0h, A0l, r * ASTR + col, v0, v1);              \
                }                                                              \
            }                                                                  \
        } while (0)

    // ---- X (= macc) -> A0 ----
    #pragma unroll
    for (int mt = 0; mt < 2; mt++)
        #pragma unroll
        for (int half = 0; half < 2; half++) {
            int r = mt * 16 + r_q + half * 8;
            #pragma unroll
            for (int nt = 0; nt < 4; nt++) {
                int col = colq + nt * 8;
                float2 v = maccS2[((mt * 2 + half) * 4 + nt) * NT + t];
                split_pair(A0h, A0l, r * ASTR + col, v.x, v.y);
            }
        }
    __syncthreads();

    // ---- parent_feat = relu(X @ W2 + b2) ----
    gemm_tc(smb, 1, lane, wn, C0);
    __syncthreads();
    FRAGS_TO_A(C0, b2S, 1);
    __syncthreads();

    // ---- enc = relu(P @ Ws1 + bs1) ----
    gemm_tc(smb, 2, lane, wn, C0);
    __syncthreads();
    FRAGS_TO_A(C0, bs1S, 1);
    __syncthreads();

    // ---- mu = enc @ Wmu + bmu (regs; A0 holds enc) ----
    gemm_tc(smb, 3, lane, wn, C0);
    float mu[2][4][4];
    #pragma unroll
    for (int mt = 0; mt < 2; mt++)
        #pragma unroll
        for (int half = 0; half < 2; half++)
            #pragma unroll
            for (int nt = 0; nt < 4; nt++) {
                int col = colq + nt * 8;
                float2 bb = *(const float2*)&bmuS[col];
                mu[mt][nt][half * 2 + 0] = C0[mt][nt][half * 2 + 0] + bb.x;
                mu[mt][nt][half * 2 + 1] = C0[mt][nt][half * 2 + 1] + bb.y;
            }

    // ---- logvar = enc @ Wvar + bvar (A0 untouched); sampler epilogue ----
    gemm_tc(smb, 4, lane, wn, C0);
    #pragma unroll
    for (int mt = 0; mt < 2; mt++)
        #pragma unroll
        for (int half = 0; half < 2; half++) {
            int r = mt * 16 + r_q + half * 8;
            int pid = permS[r];
            #pragma unroll
            for (int nt = 0; nt < 4; nt++) {
                int col = colq + nt * 8;
                float2 bb = *(const float2*)&bvarS[col];
                float2 e  = *(const float2*)&eps[pid * 256 + col];
                float lvx = C0[mt][nt][half * 2 + 0] + bb.x;
                float lvy = C0[mt][nt][half * 2 + 1] + bb.y;
                float mvx = mu[mt][nt][half * 2 + 0];
                float mvy = mu[mt][nt][half * 2 + 1];
                float sdx = expf(0.5f * lvx);
                float sdy = expf(0.5f * lvy);
                float2 samp, kld;
                samp.x = e.x * sdx + mvx;
                samp.y = e.y * sdy + mvy;
                kld.x = 1.0f + lvx - mvx * mvx - sdx * sdx;
                kld.y = 1.0f + lvy - mvy * mvy - sdy * sdy;
                *(float2*)&out[pid * 512 + col]       = samp;
                *(float2*)&out[pid * 512 + 256 + col] = kld;
            }
        }
}

// ================= launch =================
extern "C" void kernel_launch(void* const* d_in, const int* in_sizes, int n_in,
                              void* d_out, int out_size)
{
    const float* box   = (const float*)d_in[0];
    const float* eps   = (const float*)d_in[1];
    const float* W_box = (const float*)d_in[2];
    const float* b_box = (const float*)d_in[3];
    const float* W1    = (const float*)d_in[4];
    const float* b1    = (const float*)d_in[5];
    const float* W2    = (const float*)d_in[6];
    const float* b2    = (const float*)d_in[7];
    const float* Ws1   = (const float*)d_in[8];
    const float* bs1   = (const float*)d_in[9];
    const float* Wmu   = (const float*)d_in[10];
    const float* bmu   = (const float*)d_in[11];
    const float* Wvar  = (const float*)d_in[12];
    const float* bvar  = (const float*)d_in[13];
    const int*   sem   = (const int*)d_in[14];
    const int*   nc    = (const int*)d_in[15];
    float* out = (float*)d_out;

    prep_pack<<<320, 256>>>(W1, W2, Ws1, Wmu, Wvar);   // also zeroes g_cnt
    prep_pack_box<<<4, 256>>>(W_box);
    sort_count<<<B_N / 256, 256>>>(nc);
    sort_scatter<<<B_N / 256, 256>>>(nc);

    cudaFuncSetAttribute(recenc_tc_kernel,
                         cudaFuncAttributeMaxDynamicSharedMemorySize, SMEM_SZ);
    recenc_tc_kernel<<<GRID, NT, SMEM_SZ>>>(
        box, eps, W_box, b_box, W1, b1, b2, bs1, bmu, bvar, sem, nc, out);
}